// round 4
// baseline (speedup 1.0000x reference)
#include <cuda_runtime.h>

#define BB   4
#define SS   2048
#define EMBD 1024
#define NH   16
#define DHD  64
#define MTOT (BB*SS)   // 8192

// ---------------- scratch (device globals; allocation-free) ----------------
__device__ float g_Q[(size_t)BB*NH*SS*DHD];   // [b,h,s,d]
__device__ float g_K[(size_t)BB*NH*SS*DHD];
__device__ float g_V[(size_t)BB*NH*SS*DHD];
__device__ float g_C[(size_t)BB*SS*EMBD];     // context, concat layout [b,s,e]

// ---------------- f32x2 packed helpers (Blackwell FFMA2 path) ----------------
__device__ __forceinline__ unsigned long long pk2(float a, float b) {
    unsigned long long r;
    asm("mov.b64 %0, {%1, %2};" : "=l"(r)
        : "r"(__float_as_uint(a)), "r"(__float_as_uint(b)));
    return r;
}
__device__ __forceinline__ void ffma2(unsigned long long& d,
                                      unsigned long long a,
                                      unsigned long long b) {
    asm("fma.rn.f32x2 %0, %1, %2, %0;" : "+l"(d) : "l"(a), "l"(b));
}
__device__ __forceinline__ unsigned long long mul2(unsigned long long a,
                                                   unsigned long long b) {
    unsigned long long r;
    asm("mul.rn.f32x2 %0, %1, %2;" : "=l"(r) : "l"(a), "l"(b));
    return r;
}
__device__ __forceinline__ float2 up2(unsigned long long v) {
    unsigned int lo, hi;
    asm("mov.b64 {%0, %1}, %2;" : "=r"(lo), "=r"(hi) : "l"(v));
    float2 r; r.x = __uint_as_float(lo); r.y = __uint_as_float(hi);
    return r;
}
__device__ __forceinline__ float ex2f(float x) {
    float r; asm("ex2.approx.f32 %0, %1;" : "=f"(r) : "f"(x)); return r;
}

// ---------------- 128x128x16 SGEMM with f32x2 micro-kernel ----------------
// mode 0/1/2: out = A_ext @ W + bias, written split-heads into g_Q/g_K/g_V
// mode 3:     out = g_C  @ W + bias, written row-major into outp
__global__ __launch_bounds__(256, 2)
void gemm128(const float* __restrict__ Aext, const float* __restrict__ W,
             const float* __restrict__ bias, float* __restrict__ outp, int mode)
{
    __shared__ float As[16 * 132];   // [k][m], padded stride
    __shared__ float Bs[16 * 132];   // [k][n], padded stride

    const float* A = (mode == 3) ? g_C : Aext;
    const int tid = threadIdx.x;
    const int tx  = tid & 15;        // n micro
    const int ty  = tid >> 4;        // m micro
    const int m0  = blockIdx.y * 128;
    const int n0  = blockIdx.x * 128;

    unsigned long long acc[8][4];
#pragma unroll
    for (int i = 0; i < 8; i++)
#pragma unroll
        for (int j = 0; j < 4; j++) acc[i][j] = 0ull;

    for (int kt = 0; kt < EMBD / 16; kt++) {
        // A tile 128x16, stored transposed As[k][m]
#pragma unroll
        for (int i = 0; i < 2; i++) {
            int idx = tid + 256 * i;
            int m   = idx >> 2;
            int kq  = (idx & 3) << 2;
            float4 v = *(const float4*)(A + (size_t)(m0 + m) * EMBD + kt * 16 + kq);
            As[(kq + 0) * 132 + m] = v.x;
            As[(kq + 1) * 132 + m] = v.y;
            As[(kq + 2) * 132 + m] = v.z;
            As[(kq + 3) * 132 + m] = v.w;
        }
        // B tile 16x128, natural Bs[k][n]
#pragma unroll
        for (int i = 0; i < 2; i++) {
            int idx = tid + 256 * i;
            int k   = idx >> 5;
            int n4  = (idx & 31) << 2;
            *(float4*)(Bs + k * 132 + n4) =
                *(const float4*)(W + (size_t)(kt * 16 + k) * EMBD + n0 + n4);
        }
        __syncthreads();

#pragma unroll
        for (int k = 0; k < 16; k++) {
            float4 a0 = *(const float4*)(As + k * 132 + ty * 8);
            float4 a1 = *(const float4*)(As + k * 132 + ty * 8 + 4);
            ulonglong2 b0 = *(const ulonglong2*)(Bs + k * 132 + tx * 8);
            ulonglong2 b1 = *(const ulonglong2*)(Bs + k * 132 + tx * 8 + 4);
            float am[8] = {a0.x, a0.y, a0.z, a0.w, a1.x, a1.y, a1.z, a1.w};
#pragma unroll
            for (int i = 0; i < 8; i++) {
                unsigned long long aa = pk2(am[i], am[i]);
                ffma2(acc[i][0], aa, b0.x);
                ffma2(acc[i][1], aa, b0.y);
                ffma2(acc[i][2], aa, b1.x);
                ffma2(acc[i][3], aa, b1.y);
            }
        }
        __syncthreads();
    }

    // epilogue
#pragma unroll
    for (int i = 0; i < 8; i++) {
        int m = m0 + ty * 8 + i;
        int n = n0 + tx * 8;
        float c[8];
        float2 t;
        t = up2(acc[i][0]); c[0] = t.x; c[1] = t.y;
        t = up2(acc[i][1]); c[2] = t.x; c[3] = t.y;
        t = up2(acc[i][2]); c[4] = t.x; c[5] = t.y;
        t = up2(acc[i][3]); c[6] = t.x; c[7] = t.y;
#pragma unroll
        for (int j = 0; j < 8; j++) c[j] += bias[n + j];

        if (mode == 3) {
            float4* o = (float4*)(outp + (size_t)m * EMBD + n);
            o[0] = make_float4(c[0], c[1], c[2], c[3]);
            o[1] = make_float4(c[4], c[5], c[6], c[7]);
        } else {
            float* dst = (mode == 0) ? g_Q : (mode == 1) ? g_K : g_V;
            int b = m >> 11;           // S = 2048
            int s = m & (SS - 1);
            int h = n >> 6;            // DH = 64 (8-col group never crosses a head)
            int d = n & 63;
            float4* o = (float4*)(dst + (((size_t)(b * NH + h) * SS + s) * DHD + d));
            o[0] = make_float4(c[0], c[1], c[2], c[3]);
            o[1] = make_float4(c[4], c[5], c[6], c[7]);
        }
    }
}

// ---------------- flash attention, 64x64 tiles, fp32/f32x2 ----------------
// grid (S/64, H, B), 256 threads. Static smem = exactly 48KB:
//   Qt [d][q] 16KB,  KP [d][k] (reused as P [q][k]) 16KB,  Vs [k][d] 16KB
__global__ __launch_bounds__(256, 2)
void attn64()
{
    __shared__ float Qt[64 * 64];
    __shared__ float KP[64 * 64];
    __shared__ float Vs[64 * 64];

    const int tid = threadIdx.x;
    const int tx  = tid & 15;       // 4 key/dh cols
    const int ty  = tid >> 4;       // 4 query rows
    const int q0  = blockIdx.x * 64;
    const int h   = blockIdx.y;
    const int b   = blockIdx.z;

    // fold 1/sqrt(Dh) and log2(e) into Q so softmax uses ex2 directly
    const float qscale = 0.125f * 1.44269504088896340736f;
    const size_t headbase = (size_t)(b * NH + h) * SS * DHD;

    {   // load Q tile transposed [d][q], pre-scaled (one-time)
        const float* Qg = g_Q + headbase + (size_t)q0 * DHD;
#pragma unroll
        for (int i = 0; i < 4; i++) {
            int idx = tid + 256 * i;
            int q   = idx >> 4;
            int d4  = (idx & 15) << 2;
            float4 v = *(const float4*)(Qg + q * DHD + d4);
            Qt[(d4 + 0) * 64 + q] = v.x * qscale;
            Qt[(d4 + 1) * 64 + q] = v.y * qscale;
            Qt[(d4 + 2) * 64 + q] = v.z * qscale;
            Qt[(d4 + 3) * 64 + q] = v.w * qscale;
        }
    }

    unsigned long long oacc[4][2];
    float mrow[4], lrow[4];
#pragma unroll
    for (int i = 0; i < 4; i++) {
        oacc[i][0] = 0ull; oacc[i][1] = 0ull;
        mrow[i] = -3.0e38f; lrow[i] = 0.0f;
    }

    for (int kt = 0; kt < SS / 64; kt++) {
        __syncthreads();   // previous PV done before K/V overwrite
        const float* Kg = g_K + headbase + (size_t)(kt * 64) * DHD;
        const float* Vg = g_V + headbase + (size_t)(kt * 64) * DHD;
#pragma unroll
        for (int i = 0; i < 4; i++) {
            int idx = tid + 256 * i;
            int r   = idx >> 4;
            int d4  = (idx & 15) << 2;
            float4 kv = *(const float4*)(Kg + r * DHD + d4);
            KP[(d4 + 0) * 64 + r] = kv.x;
            KP[(d4 + 1) * 64 + r] = kv.y;
            KP[(d4 + 2) * 64 + r] = kv.z;
            KP[(d4 + 3) * 64 + r] = kv.w;
            *(float4*)(Vs + r * 64 + d4) = *(const float4*)(Vg + r * DHD + d4);
        }
        __syncthreads();

        // scores: s[i][j] = sum_d Qt[d][ty*4+i] * KP[d][tx*4+j]
        unsigned long long sacc[4][2];
#pragma unroll
        for (int i = 0; i < 4; i++) { sacc[i][0] = 0ull; sacc[i][1] = 0ull; }
#pragma unroll
        for (int d = 0; d < 64; d++) {
            float4 qv = *(const float4*)(Qt + d * 64 + ty * 4);
            ulonglong2 kb = *(const ulonglong2*)(KP + d * 64 + tx * 4);
            float qa[4] = {qv.x, qv.y, qv.z, qv.w};
#pragma unroll
            for (int i = 0; i < 4; i++) {
                unsigned long long aa = pk2(qa[i], qa[i]);
                ffma2(sacc[i][0], aa, kb.x);
                ffma2(sacc[i][1], aa, kb.y);
            }
        }
        __syncthreads();   // everyone done reading KP(K) before P overwrites it

        // online softmax (base-2) + write P into KP as [q][k]
#pragma unroll
        for (int i = 0; i < 4; i++) {
            float2 s01 = up2(sacc[i][0]);
            float2 s23 = up2(sacc[i][1]);
            float s[4] = {s01.x, s01.y, s23.x, s23.y};
            float rm = fmaxf(fmaxf(s[0], s[1]), fmaxf(s[2], s[3]));
#pragma unroll
            for (int off = 1; off < 16; off <<= 1)
                rm = fmaxf(rm, __shfl_xor_sync(0xffffffffu, rm, off));
            float mn = fmaxf(mrow[i], rm);
            float corr = ex2f(mrow[i] - mn);
            mrow[i] = mn;
            float p[4], rs = 0.0f;
#pragma unroll
            for (int j = 0; j < 4; j++) { p[j] = ex2f(s[j] - mn); rs += p[j]; }
#pragma unroll
            for (int off = 1; off < 16; off <<= 1)
                rs += __shfl_xor_sync(0xffffffffu, rs, off);
            lrow[i] = lrow[i] * corr + rs;
            unsigned long long cc = pk2(corr, corr);
            oacc[i][0] = mul2(oacc[i][0], cc);
            oacc[i][1] = mul2(oacc[i][1], cc);
            *(float4*)(KP + (ty * 4 + i) * 64 + tx * 4) =
                make_float4(p[0], p[1], p[2], p[3]);
        }
        __syncthreads();

        // PV: oacc[i] += sum_k P[ty*4+i][k] * V[k][tx*4..tx*4+3]
#pragma unroll
        for (int k0 = 0; k0 < 64; k0 += 4) {
            float pa[4][4];
#pragma unroll
            for (int i = 0; i < 4; i++) {
                float4 pr = *(const float4*)(KP + (ty * 4 + i) * 64 + k0);
                pa[i][0] = pr.x; pa[i][1] = pr.y; pa[i][2] = pr.z; pa[i][3] = pr.w;
            }
#pragma unroll
            for (int kk = 0; kk < 4; kk++) {
                ulonglong2 vb = *(const ulonglong2*)(Vs + (k0 + kk) * 64 + tx * 4);
#pragma unroll
                for (int i = 0; i < 4; i++) {
                    unsigned long long aa = pk2(pa[i][kk], pa[i][kk]);
                    ffma2(oacc[i][0], aa, vb.x);
                    ffma2(oacc[i][1], aa, vb.y);
                }
            }
        }
    }

    // normalize + write context in concat layout [b, s, h*64 + d]
#pragma unroll
    for (int i = 0; i < 4; i++) {
        float rl = 1.0f / lrow[i];
        float2 x0 = up2(oacc[i][0]);
        float2 x1 = up2(oacc[i][1]);
        size_t off = ((size_t)b * SS + q0 + ty * 4 + i) * EMBD + h * DHD + tx * 4;
        *(float4*)(g_C + off) = make_float4(x0.x * rl, x0.y * rl, x1.x * rl, x1.y * rl);
    }
}

// ---------------- launch ----------------
extern "C" void kernel_launch(void* const* d_in, const int* in_sizes, int n_in,
                              void* d_out, int out_size)
{
    (void)in_sizes; (void)n_in; (void)out_size;
    const float* x  = (const float*)d_in[0];
    const float* Wq = (const float*)d_in[1];
    const float* bq = (const float*)d_in[2];
    const float* Wk = (const float*)d_in[3];
    const float* bk = (const float*)d_in[4];
    const float* Wv = (const float*)d_in[5];
    const float* bv = (const float*)d_in[6];
    const float* Wo = (const float*)d_in[7];
    const float* bo = (const float*)d_in[8];
    float* out = (float*)d_out;

    dim3 gg(EMBD / 128, MTOT / 128, 1);
    gemm128<<<gg, 256>>>(x, Wq, bq, nullptr, 0);
    gemm128<<<gg, 256>>>(x, Wk, bk, nullptr, 1);
    gemm128<<<gg, 256>>>(x, Wv, bv, nullptr, 2);
    attn64<<<dim3(SS / 64, NH, BB), 256>>>();
    gemm128<<<gg, 256>>>(nullptr, Wo, bo, out, 3);
}

// round 6
// speedup vs baseline: 1.9889x; 1.9889x over previous
#include <cuda_runtime.h>

#define BB   4
#define SS   2048
#define EMBD 1024
#define NH   16
#define DHD  64
#define MTOT (BB*SS)   // 8192

// ---------------- scratch (device globals; allocation-free) ----------------
__device__ float g_Qt[(size_t)BB*NH*DHD*SS];  // [b,h,d,s]  (d-major!)
__device__ float g_Kt[(size_t)BB*NH*DHD*SS];  // [b,h,d,s]
__device__ float g_V [(size_t)BB*NH*SS*DHD];  // [b,h,s,d]
__device__ float g_C [(size_t)BB*SS*EMBD];    // context [b,s,e]

// ---------------- f32x2 packed helpers ----------------
__device__ __forceinline__ unsigned long long pk2(float a, float b) {
    unsigned long long r;
    asm("mov.b64 %0, {%1, %2};" : "=l"(r)
        : "r"(__float_as_uint(a)), "r"(__float_as_uint(b)));
    return r;
}
__device__ __forceinline__ void ffma2(unsigned long long& d,
                                      unsigned long long a,
                                      unsigned long long b) {
    asm("fma.rn.f32x2 %0, %1, %2, %0;" : "+l"(d) : "l"(a), "l"(b));
}
__device__ __forceinline__ unsigned long long mul2(unsigned long long a,
                                                   unsigned long long b) {
    unsigned long long r;
    asm("mul.rn.f32x2 %0, %1, %2;" : "=l"(r) : "l"(a), "l"(b));
    return r;
}
__device__ __forceinline__ void add2(unsigned long long& d, unsigned long long a) {
    asm("add.rn.f32x2 %0, %0, %1;" : "+l"(d) : "l"(a));
}
__device__ __forceinline__ float2 up2(unsigned long long v) {
    unsigned int lo, hi;
    asm("mov.b64 {%0, %1}, %2;" : "=r"(lo), "=r"(hi) : "l"(v));
    float2 r; r.x = __uint_as_float(lo); r.y = __uint_as_float(hi);
    return r;
}
__device__ __forceinline__ float ex2f(float x) {
    float r; asm("ex2.approx.f32 %0, %1;" : "=f"(r) : "f"(x)); return r;
}

// ---------------- shared GEMM core: 128x128 tile, K-step 16, double-buffered ----------------
// A row-major [*,1024], W row-major [1024,1024]. Result c[8][8] per thread.
__device__ __forceinline__ void gemm_core(const float* __restrict__ A,
                                          const float* __restrict__ W,
                                          float (*As)[16*132], float (*Bs)[16*132],
                                          int m0, int n0, int tid,
                                          float (&c)[8][8])
{
    const int tx  = tid & 15;
    const int ty  = tid >> 4;
    const int am  = tid >> 2;          // 0..63
    const int am2 = am + 64;
    const int ak  = (tid & 3) << 2;    // k-quad
    const int bk0 = tid >> 5;          // 0..7
    const int bk1 = bk0 + 8;
    const int bn  = (tid & 31) << 2;

    unsigned long long acc[8][4];
#pragma unroll
    for (int i = 0; i < 8; i++)
#pragma unroll
        for (int j = 0; j < 4; j++) acc[i][j] = 0ull;

    float4 ra0, ra1, rb0, rb1;

    // prologue: tile 0
    ra0 = *(const float4*)(A + (size_t)(m0 + am ) * EMBD + ak);
    ra1 = *(const float4*)(A + (size_t)(m0 + am2) * EMBD + ak);
    rb0 = *(const float4*)(W + (size_t)bk0 * EMBD + n0 + bn);
    rb1 = *(const float4*)(W + (size_t)bk1 * EMBD + n0 + bn);
    {
        float* Ad = As[0]; float* Bd = Bs[0];
        Ad[(ak+0)*132+am ] = ra0.x; Ad[(ak+1)*132+am ] = ra0.y;
        Ad[(ak+2)*132+am ] = ra0.z; Ad[(ak+3)*132+am ] = ra0.w;
        Ad[(ak+0)*132+am2] = ra1.x; Ad[(ak+1)*132+am2] = ra1.y;
        Ad[(ak+2)*132+am2] = ra1.z; Ad[(ak+3)*132+am2] = ra1.w;
        *(float4*)(Bd + bk0*132 + bn) = rb0;
        *(float4*)(Bd + bk1*132 + bn) = rb1;
    }
    __syncthreads();

    for (int kt = 0; kt < EMBD/16; kt++) {
        const int cur = kt & 1;
        if (kt < EMBD/16 - 1) {   // prefetch next tile into registers
            const int kn = kt + 1;
            ra0 = *(const float4*)(A + (size_t)(m0 + am ) * EMBD + kn*16 + ak);
            ra1 = *(const float4*)(A + (size_t)(m0 + am2) * EMBD + kn*16 + ak);
            rb0 = *(const float4*)(W + (size_t)(kn*16 + bk0) * EMBD + n0 + bn);
            rb1 = *(const float4*)(W + (size_t)(kn*16 + bk1) * EMBD + n0 + bn);
        }
        const float* Ab = As[cur];
        const float* Bb = Bs[cur];
#pragma unroll 8
        for (int k = 0; k < 16; k++) {
            float4 a0 = *(const float4*)(Ab + k*132 + ty*8);
            float4 a1 = *(const float4*)(Ab + k*132 + ty*8 + 4);
            ulonglong2 b0 = *(const ulonglong2*)(Bb + k*132 + tx*8);
            ulonglong2 b1 = *(const ulonglong2*)(Bb + k*132 + tx*8 + 4);
            float aq[8] = {a0.x, a0.y, a0.z, a0.w, a1.x, a1.y, a1.z, a1.w};
#pragma unroll
            for (int i = 0; i < 8; i++) {
                unsigned long long aa = pk2(aq[i], aq[i]);
                ffma2(acc[i][0], aa, b0.x);
                ffma2(acc[i][1], aa, b0.y);
                ffma2(acc[i][2], aa, b1.x);
                ffma2(acc[i][3], aa, b1.y);
            }
        }
        __syncthreads();
        if (kt < EMBD/16 - 1) {
            float* Ad = As[cur ^ 1]; float* Bd = Bs[cur ^ 1];
            Ad[(ak+0)*132+am ] = ra0.x; Ad[(ak+1)*132+am ] = ra0.y;
            Ad[(ak+2)*132+am ] = ra0.z; Ad[(ak+3)*132+am ] = ra0.w;
            Ad[(ak+0)*132+am2] = ra1.x; Ad[(ak+1)*132+am2] = ra1.y;
            Ad[(ak+2)*132+am2] = ra1.z; Ad[(ak+3)*132+am2] = ra1.w;
            *(float4*)(Bd + bk0*132 + bn) = rb0;
            *(float4*)(Bd + bk1*132 + bn) = rb1;
            __syncthreads();
        }
    }

#pragma unroll
    for (int i = 0; i < 8; i++) {
        float2 t;
        t = up2(acc[i][0]); c[i][0] = t.x; c[i][1] = t.y;
        t = up2(acc[i][1]); c[i][2] = t.x; c[i][3] = t.y;
        t = up2(acc[i][2]); c[i][4] = t.x; c[i][5] = t.y;
        t = up2(acc[i][3]); c[i][6] = t.x; c[i][7] = t.y;
    }
}

// ---------------- QKV projection (merged, z = 0:Q 1:K 2:V) ----------------
__global__ __launch_bounds__(256, 2)
void gemm_qkv(const float* __restrict__ x,
              const float* __restrict__ Wq, const float* __restrict__ bq,
              const float* __restrict__ Wk, const float* __restrict__ bk,
              const float* __restrict__ Wv, const float* __restrict__ bv)
{
    __shared__ float As[2][16*132];
    __shared__ float Bs[2][16*132];

    const int z = blockIdx.z;
    const float* W    = (z == 0) ? Wq : (z == 1) ? Wk : Wv;
    const float* bias = (z == 0) ? bq : (z == 1) ? bk : bv;

    const int tid = threadIdx.x;
    const int tx  = tid & 15;
    const int ty  = tid >> 4;
    const int m0  = blockIdx.y * 128;
    const int n0  = blockIdx.x * 128;

    float c[8][8];
    gemm_core(x, W, As, Bs, m0, n0, tid, c);

#pragma unroll
    for (int i = 0; i < 8; i++)
#pragma unroll
        for (int j = 0; j < 8; j++) c[i][j] += bias[n0 + tx*8 + j];

    const int b = m0 >> 11;
    const int s = (m0 & (SS-1)) + ty * 8;
    if (z < 2) {
        // transposed store: dst[b,h,d,s]
        float* dst = z ? g_Kt : g_Qt;
#pragma unroll
        for (int j = 0; j < 8; j++) {
            int n = n0 + tx*8 + j;
            int h = n >> 6, d = n & 63;
            float* p = dst + ((size_t)(b*NH + h)*DHD + d)*SS + s;
            *(float4*)(p)     = make_float4(c[0][j], c[1][j], c[2][j], c[3][j]);
            *(float4*)(p + 4) = make_float4(c[4][j], c[5][j], c[6][j], c[7][j]);
        }
    } else {
        // natural store: g_V[b,h,s,d]
#pragma unroll
        for (int i = 0; i < 8; i++) {
            int n = n0 + tx*8;
            int h = n >> 6, d = n & 63;
            float* p = g_V + ((size_t)(b*NH + h)*SS + s + i)*DHD + d;
            *(float4*)(p)     = make_float4(c[i][0], c[i][1], c[i][2], c[i][3]);
            *(float4*)(p + 4) = make_float4(c[i][4], c[i][5], c[i][6], c[i][7]);
        }
    }
}

// ---------------- output projection: out = g_C @ Wo + bo ----------------
__global__ __launch_bounds__(256, 2)
void gemm_out(const float* __restrict__ Wo, const float* __restrict__ bo,
              float* __restrict__ outp)
{
    __shared__ float As[2][16*132];
    __shared__ float Bs[2][16*132];

    const int tid = threadIdx.x;
    const int tx  = tid & 15;
    const int ty  = tid >> 4;
    const int m0  = blockIdx.y * 128;
    const int n0  = blockIdx.x * 128;

    float c[8][8];
    gemm_core(g_C, Wo, As, Bs, m0, n0, tid, c);

#pragma unroll
    for (int i = 0; i < 8; i++) {
        int m = m0 + ty*8 + i;
        int n = n0 + tx*8;
        float* p = outp + (size_t)m * EMBD + n;
        *(float4*)(p)     = make_float4(c[i][0] + bo[n],   c[i][1] + bo[n+1],
                                        c[i][2] + bo[n+2], c[i][3] + bo[n+3]);
        *(float4*)(p + 4) = make_float4(c[i][4] + bo[n+4], c[i][5] + bo[n+5],
                                        c[i][6] + bo[n+6], c[i][7] + bo[n+7]);
    }
}

// ---------------- flash attention: 128q x 128k tiles, 8x8 micro ----------------
// Dynamic smem layout (floats):
//   Qt[64][128]  8192   (d-major, pre-scaled)
//   Kt[64][128]  8192   (d-major)
//   Vs[128][68]  8704   (padded stride 68)
//   P [128][132] 16896
#define QTS 128
#define VSS 68
#define PS  132
#define SMEM_FLOATS (64*QTS + 64*QTS + 128*VSS + 128*PS)

__global__ __launch_bounds__(256, 1)
void attn128()
{
    extern __shared__ float sm[];
    float* Qt = sm;
    float* Kt = Qt + 64*QTS;
    float* Vs = Kt + 64*QTS;
    float* P  = Vs + 128*VSS;

    const int tid  = threadIdx.x;
    const int tx   = tid & 15;
    const int ty   = tid >> 4;
    const int txLo = tx & 7;
    const int txHi = tx >> 3;
    const int q0   = blockIdx.x * 128;
    const int h    = blockIdx.y;
    const int b    = blockIdx.z;

    const float qscale = 0.125f * 1.44269504088896340736f;  // 1/sqrt(64) * log2(e)
    const size_t hb_t = (size_t)(b*NH + h) * DHD * SS;      // g_Qt/g_Kt head base
    const size_t hb_v = (size_t)(b*NH + h) * SS * DHD;      // g_V head base

    {   // load Q tile [64][128] (already d-major), pre-scaled
        const float* Qg = g_Qt + hb_t + q0;
#pragma unroll
        for (int i = 0; i < 8; i++) {
            int idx = tid + 256*i;
            int d = idx >> 5;
            int c4 = (idx & 31) << 2;
            float4 v = *(const float4*)(Qg + (size_t)d*SS + c4);
            v.x *= qscale; v.y *= qscale; v.z *= qscale; v.w *= qscale;
            *(float4*)(Qt + d*QTS + c4) = v;
        }
    }

    unsigned long long oacc[8][4];
    float mrow[8], lrow[8];
#pragma unroll
    for (int i = 0; i < 8; i++) {
        oacc[i][0] = oacc[i][1] = oacc[i][2] = oacc[i][3] = 0ull;
        mrow[i] = -3.0e38f; lrow[i] = 0.0f;
    }

    for (int kt = 0; kt < SS/128; kt++) {
        __syncthreads();    // prev PV done reading Vs/P before overwrite
        {   // K tile [64][128] d-major (no transpose needed)
            const float* Kg = g_Kt + hb_t + kt*128;
#pragma unroll
            for (int i = 0; i < 8; i++) {
                int idx = tid + 256*i;
                int d = idx >> 5;
                int c4 = (idx & 31) << 2;
                *(float4*)(Kt + d*QTS + c4) = *(const float4*)(Kg + (size_t)d*SS + c4);
            }
            // V tile [128][64] natural
            const float* Vg = g_V + hb_v + (size_t)(kt*128)*DHD;
#pragma unroll
            for (int i = 0; i < 8; i++) {
                int idx = tid + 256*i;
                int r = idx >> 4;
                int d4 = (idx & 15) << 2;
                *(float4*)(Vs + r*VSS + d4) = *(const float4*)(Vg + r*DHD + d4);
            }
        }
        __syncthreads();

        // ---- scores: s[i][j] = sum_d Qt[d][ty*8+i] * Kt[d][tx*8+j] ----
        unsigned long long sacc[8][4];
#pragma unroll
        for (int i = 0; i < 8; i++)
            sacc[i][0] = sacc[i][1] = sacc[i][2] = sacc[i][3] = 0ull;
#pragma unroll 8
        for (int d = 0; d < 64; d++) {
            float4 a0 = *(const float4*)(Qt + d*QTS + ty*8);
            float4 a1 = *(const float4*)(Qt + d*QTS + ty*8 + 4);
            ulonglong2 b0 = *(const ulonglong2*)(Kt + d*QTS + tx*8);
            ulonglong2 b1 = *(const ulonglong2*)(Kt + d*QTS + tx*8 + 4);
            float aq[8] = {a0.x, a0.y, a0.z, a0.w, a1.x, a1.y, a1.z, a1.w};
#pragma unroll
            for (int i = 0; i < 8; i++) {
                unsigned long long aa = pk2(aq[i], aq[i]);
                ffma2(sacc[i][0], aa, b0.x);
                ffma2(sacc[i][1], aa, b0.y);
                ffma2(sacc[i][2], aa, b1.x);
                ffma2(sacc[i][3], aa, b1.y);
            }
        }

        // ---- online softmax (base-2) per q row; write P ----
#pragma unroll
        for (int i = 0; i < 8; i++) {
            float2 s01 = up2(sacc[i][0]), s23 = up2(sacc[i][1]);
            float2 s45 = up2(sacc[i][2]), s67 = up2(sacc[i][3]);
            float s[8] = {s01.x, s01.y, s23.x, s23.y, s45.x, s45.y, s67.x, s67.y};
            float rm = s[0];
#pragma unroll
            for (int j = 1; j < 8; j++) rm = fmaxf(rm, s[j]);
#pragma unroll
            for (int off = 1; off < 16; off <<= 1)
                rm = fmaxf(rm, __shfl_xor_sync(0xffffffffu, rm, off));
            float mn = fmaxf(mrow[i], rm);
            float corr = ex2f(mrow[i] - mn);
            mrow[i] = mn;
            float p[8], rs = 0.0f;
#pragma unroll
            for (int j = 0; j < 8; j++) { p[j] = ex2f(s[j] - mn); rs += p[j]; }
#pragma unroll
            for (int off = 1; off < 16; off <<= 1)
                rs += __shfl_xor_sync(0xffffffffu, rs, off);
            lrow[i] = lrow[i] * corr + rs;
            unsigned long long cc = pk2(corr, corr);
            oacc[i][0] = mul2(oacc[i][0], cc);
            oacc[i][1] = mul2(oacc[i][1], cc);
            oacc[i][2] = mul2(oacc[i][2], cc);
            oacc[i][3] = mul2(oacc[i][3], cc);
            *(float4*)(P + (ty*8 + i)*PS + tx*8)     = make_float4(p[0], p[1], p[2], p[3]);
            *(float4*)(P + (ty*8 + i)*PS + tx*8 + 4) = make_float4(p[4], p[5], p[6], p[7]);
        }
        __syncthreads();

        // ---- PV (split-K by txHi): oacc[i][d8] += sum_{k half} P[q][k] * V[k][d8] ----
#pragma unroll 2
        for (int kb = 0; kb < 16; kb++) {
            const int kbase = txHi*64 + kb*4;
            float4 pr[8];
#pragma unroll
            for (int i = 0; i < 8; i++)
                pr[i] = *(const float4*)(P + (ty*8 + i)*PS + kbase);
#pragma unroll
            for (int kk = 0; kk < 4; kk++) {
                const float* vrow = Vs + (kbase + kk)*VSS + txLo*8;
                ulonglong2 v0 = *(const ulonglong2*)(vrow);
                ulonglong2 v1 = *(const ulonglong2*)(vrow + 4);
#pragma unroll
                for (int i = 0; i < 8; i++) {
                    float pv = (kk == 0) ? pr[i].x : (kk == 1) ? pr[i].y
                             : (kk == 2) ? pr[i].z : pr[i].w;
                    unsigned long long aa = pk2(pv, pv);
                    ffma2(oacc[i][0], aa, v0.x);
                    ffma2(oacc[i][1], aa, v0.y);
                    ffma2(oacc[i][2], aa, v1.x);
                    ffma2(oacc[i][3], aa, v1.y);
                }
            }
        }
    }

    // combine the two split-K halves (f32x2 add, lane-xor 8)
#pragma unroll
    for (int i = 0; i < 8; i++)
#pragma unroll
        for (int c = 0; c < 4; c++) {
            unsigned long long other = __shfl_xor_sync(0xffffffffu, oacc[i][c], 8);
            add2(oacc[i][c], other);
        }

    if (txHi == 0) {
#pragma unroll
        for (int i = 0; i < 8; i++) {
            float rl = 1.0f / lrow[i];
            float2 p0 = up2(oacc[i][0]), p1 = up2(oacc[i][1]);
            float2 p2 = up2(oacc[i][2]), p3 = up2(oacc[i][3]);
            float* dst = g_C + ((size_t)b*SS + q0 + ty*8 + i)*EMBD + h*DHD + txLo*8;
            *(float4*)(dst)     = make_float4(p0.x*rl, p0.y*rl, p1.x*rl, p1.y*rl);
            *(float4*)(dst + 4) = make_float4(p2.x*rl, p2.y*rl, p3.x*rl, p3.y*rl);
        }
    }
}

// ---------------- launch ----------------
extern "C" void kernel_launch(void* const* d_in, const int* in_sizes, int n_in,
                              void* d_out, int out_size)
{
    (void)in_sizes; (void)n_in; (void)out_size;
    const float* x  = (const float*)d_in[0];
    const float* Wq = (const float*)d_in[1];
    const float* bq = (const float*)d_in[2];
    const float* Wk = (const float*)d_in[3];
    const float* bk = (const float*)d_in[4];
    const float* Wv = (const float*)d_in[5];
    const float* bv = (const float*)d_in[6];
    const float* Wo = (const float*)d_in[7];
    const float* bo = (const float*)d_in[8];
    float* out = (float*)d_out;

    static int smem_set = 0;
    if (!smem_set) {
        cudaFuncSetAttribute(attn128, cudaFuncAttributeMaxDynamicSharedMemorySize,
                             SMEM_FLOATS * (int)sizeof(float));
        smem_set = 1;
    }

    gemm_qkv<<<dim3(EMBD/128, MTOT/128, 3), 256>>>(x, Wq, bq, Wk, bk, Wv, bv);
    attn128<<<dim3(SS/128, NH, BB), 256, SMEM_FLOATS * sizeof(float)>>>();
    gemm_out<<<dim3(EMBD/128, MTOT/128, 1), 256>>>(Wo, bo, out);
}

// round 8
// speedup vs baseline: 2.7279x; 1.3716x over previous
#include <cuda_runtime.h>
#include <cstdint>

#define BB   4
#define SS   2048
#define EMBD 1024
#define NH   16
#define DHD  64
#define MTOT (BB*SS)   // 8192

// ---------------- scratch (device globals; allocation-free) ----------------
__device__ float g_Qt[(size_t)BB*NH*DHD*SS];  // [b,h,d,s]  (d-major)
__device__ float g_Kt[(size_t)BB*NH*DHD*SS];  // [b,h,d,s]
__device__ float g_V [(size_t)BB*NH*SS*DHD];  // [b,h,s,d]
__device__ float g_C [(size_t)BB*SS*EMBD];    // context [b,s,e]

// split-bf16 operands (hi = trunc16(a), lo = rn(a - hi))
__device__ unsigned short g_xhi[(size_t)MTOT*EMBD], g_xlo[(size_t)MTOT*EMBD];
__device__ unsigned short g_whi[(size_t)4*EMBD*EMBD], g_wlo[(size_t)4*EMBD*EMBD]; // [which][n][k] (W^T)
__device__ unsigned short g_chi[(size_t)MTOT*EMBD], g_clo[(size_t)MTOT*EMBD];

// ================= small PTX helpers =================
__device__ __forceinline__ uint32_t smem_u32(const void* p) {
    uint32_t a;
    asm("{ .reg .u64 t; cvta.to.shared.u64 t, %1; cvt.u32.u64 %0, t; }" : "=r"(a) : "l"(p));
    return a;
}
__device__ __forceinline__ void ldmx4(uint32_t* r, uint32_t addr) {
    asm volatile("ldmatrix.sync.aligned.m8n8.x4.shared.b16 {%0,%1,%2,%3}, [%4];"
        : "=r"(r[0]), "=r"(r[1]), "=r"(r[2]), "=r"(r[3]) : "r"(addr));
}
__device__ __forceinline__ void mma16816(float* d, const uint32_t* a, const uint32_t* b) {
    asm volatile("mma.sync.aligned.m16n8k16.row.col.f32.bf16.bf16.f32 "
        "{%0,%1,%2,%3}, {%4,%5,%6,%7}, {%8,%9}, {%0,%1,%2,%3};"
        : "+f"(d[0]), "+f"(d[1]), "+f"(d[2]), "+f"(d[3])
        : "r"(a[0]), "r"(a[1]), "r"(a[2]), "r"(a[3]), "r"(b[0]), "r"(b[1]));
}
#define CPA(dst, src) asm volatile("cp.async.cg.shared.global [%0], [%1], 16;" \
                                   :: "r"(dst), "l"(src) : "memory")
#define CPC()  asm volatile("cp.async.commit_group;" ::: "memory")
#define CPW1() asm volatile("cp.async.wait_group 1;" ::: "memory")
#define CPW0() asm volatile("cp.async.wait_group 0;" ::: "memory")

// ================= conversion kernels =================
// sel 0: x(ext fp32) -> g_xhi/g_xlo ; sel 1: g_C -> g_chi/g_clo
__global__ void conv_split(const float* __restrict__ src_ext, int sel)
{
    const float* src = sel ? g_C : src_ext;
    unsigned int* hi = (unsigned int*)(sel ? g_chi : g_xhi);
    unsigned int* lo = (unsigned int*)(sel ? g_clo : g_xlo);
    const size_t nP = (size_t)MTOT * EMBD / 2;
    for (size_t p = (size_t)blockIdx.x * blockDim.x + threadIdx.x; p < nP;
         p += (size_t)gridDim.x * blockDim.x) {
        float2 v = ((const float2*)src)[p];
        unsigned int hx = __float_as_uint(v.x), hy = __float_as_uint(v.y);
        unsigned int hip = __byte_perm(hx, hy, 0x7632);   // {hi16(x), hi16(y)}
        float fx = __uint_as_float(hx & 0xFFFF0000u);
        float fy = __uint_as_float(hy & 0xFFFF0000u);
        float lx = v.x - fx, ly = v.y - fy;
        unsigned int lop;
        asm("cvt.rn.bf16x2.f32 %0, %1, %2;" : "=r"(lop) : "f"(ly), "f"(lx));
        hi[p] = hip; lo[p] = lop;
    }
}

// W [K,N] fp32 -> transposed split-bf16 [which][n][k]
__global__ void conv_wT(const float* __restrict__ W, int which)
{
    __shared__ float sm[32][33];
    const int tx = threadIdx.x, ty = threadIdx.y;       // 32 x 8
    const int n0 = blockIdx.x * 32, k0 = blockIdx.y * 32;
#pragma unroll
    for (int i = 0; i < 4; i++)
        sm[ty + 8*i][tx] = W[(size_t)(k0 + ty + 8*i) * EMBD + n0 + tx];
    __syncthreads();
    unsigned short* ho = g_whi + (size_t)which * EMBD * EMBD;
    unsigned short* lo = g_wlo + (size_t)which * EMBD * EMBD;
#pragma unroll
    for (int i = 0; i < 4; i++) {
        int n = n0 + ty + 8*i, k = k0 + tx;
        float v = sm[tx][ty + 8*i];
        unsigned int u = __float_as_uint(v);
        float hf = __uint_as_float(u & 0xFFFF0000u);
        float lv = v - hf;
        unsigned short ls;
        asm("cvt.rn.bf16.f32 %0, %1;" : "=h"(ls) : "f"(lv));
        ho[(size_t)n * EMBD + k] = (unsigned short)(u >> 16);
        lo[(size_t)n * EMBD + k] = ls;
    }
}

// ================= mma.sync split-bf16 GEMM =================
// C[128,128] tile = A @ W + bias. 8 warps, each 32x64. K-chunks of 32, cp.async 2-stage.
// smem per stage: Ahi|Alo|Bhi|Blo, each 128 rows x 32 bf16, row stride 40 shorts (80B).
#define KCH     32
#define NCH     (EMBD / KCH)     // 32
#define TROWB   80               // bytes per smem row
#define TILEB   (128 * TROWB)    // 10240
#define STGB    (4 * TILEB)      // 40960
#define GEMM_SMEM (2 * STGB)     // 81920 (epilogue reuses: 128*132*4 = 67584 <= this)

__device__ __forceinline__ void issue_stage(uint32_t sb, int s,
    const unsigned short* __restrict__ Ahi, const unsigned short* __restrict__ Alo,
    const unsigned short* __restrict__ Bhi, const unsigned short* __restrict__ Blo,
    int m0, int n0, int kc, int tid)
{
    const uint32_t base = sb + s * STGB;
    const int koff = kc * KCH;
#pragma unroll
    for (int i = 0; i < 2; i++) {
        int lin = tid + 256 * i;
        int r = lin >> 2, u = lin & 3;
        uint32_t doff = (uint32_t)(r * TROWB + u * 16);
        size_t gA = (size_t)(m0 + r) * EMBD + koff + u * 8;
        size_t gB = (size_t)(n0 + r) * EMBD + koff + u * 8;
        CPA(base + doff,             Ahi + gA);
        CPA(base + TILEB + doff,     Alo + gA);
        CPA(base + 2*TILEB + doff,   Bhi + gB);
        CPA(base + 3*TILEB + doff,   Blo + gB);
    }
    CPC();
}

__global__ void gemm_mma(int whichBase,
             const float* __restrict__ bq, const float* __restrict__ bk,
             const float* __restrict__ bv, const float* __restrict__ bo,
             float* __restrict__ outp)
{
    extern __shared__ char smg[];
    const int tid  = threadIdx.x;
    const int lane = tid & 31, wid = tid >> 5;
    const int wm = (wid & 3) * 32;      // warp m offset in tile
    const int wn = (wid >> 2) * 64;     // warp n offset in tile
    const int which = whichBase + blockIdx.z;
    const int n0 = blockIdx.x * 128, m0 = blockIdx.y * 128;
    const uint32_t sb = smem_u32(smg);

    const unsigned short* Ahi = (which == 3) ? g_chi : g_xhi;
    const unsigned short* Alo = (which == 3) ? g_clo : g_xlo;
    const unsigned short* Bhi = g_whi + (size_t)which * EMBD * EMBD;
    const unsigned short* Blo = g_wlo + (size_t)which * EMBD * EMBD;
    const float* bias = (which == 0) ? bq : (which == 1) ? bk : (which == 2) ? bv : bo;

    float acc[2][8][4];
#pragma unroll
    for (int i = 0; i < 2; i++)
#pragma unroll
        for (int j = 0; j < 8; j++)
#pragma unroll
            for (int r = 0; r < 4; r++) acc[i][j][r] = 0.0f;

    // per-lane ldmatrix base offsets (within a tile, bytes)
    // A (row-major m x k): row = (lane&15), k half = lane>>4
    const uint32_t aOff = (uint32_t)((lane & 15) * TROWB + ((lane >> 4) << 4));
    // B ([n][k]): row = (lane&7) + ((lane>>4)<<3), k half = (lane>>3)&1
    const uint32_t bOff = (uint32_t)(((lane & 7) + ((lane >> 4) << 3)) * TROWB
                                     + (((lane >> 3) & 1) << 4));

    issue_stage(sb, 0, Ahi, Alo, Bhi, Blo, m0, n0, 0, tid);

    for (int kc = 0; kc < NCH; kc++) {
        const int s = kc & 1;
        if (kc + 1 < NCH) {
            issue_stage(sb, s ^ 1, Ahi, Alo, Bhi, Blo, m0, n0, kc + 1, tid);
            CPW1();
        } else {
            CPW0();
        }
        __syncthreads();

        const uint32_t stg = sb + s * STGB;
#pragma unroll
        for (int k16 = 0; k16 < 2; k16++) {
            const uint32_t kb = k16 * 32;     // 16 shorts = 32 bytes
            uint32_t ah[2][4], al[2][4], bh[4][4], bl[4][4];
#pragma unroll
            for (int i = 0; i < 2; i++) {
                uint32_t ra = stg + (uint32_t)((wm + i * 16) * TROWB) + kb + aOff;
                ldmx4(ah[i], ra);
                ldmx4(al[i], ra + TILEB);
            }
#pragma unroll
            for (int jj = 0; jj < 4; jj++) {
                uint32_t rb = stg + 2*TILEB + (uint32_t)((wn + jj * 16) * TROWB) + kb + bOff;
                ldmx4(bh[jj], rb);
                ldmx4(bl[jj], rb + TILEB);
            }
#pragma unroll
            for (int i = 0; i < 2; i++)
#pragma unroll
                for (int jj = 0; jj < 4; jj++) {
                    mma16816(acc[i][2*jj],   ah[i], &bh[jj][0]);   // hi*hi
                    mma16816(acc[i][2*jj+1], ah[i], &bh[jj][2]);
                    mma16816(acc[i][2*jj],   ah[i], &bl[jj][0]);   // hi*lo
                    mma16816(acc[i][2*jj+1], ah[i], &bl[jj][2]);
                    mma16816(acc[i][2*jj],   al[i], &bh[jj][0]);   // lo*hi
                    mma16816(acc[i][2*jj+1], al[i], &bh[jj][2]);
                }
        }
        __syncthreads();
    }

    // ---- stage fp32 tile through smem for coalesced, layout-flexible stores ----
    float* Cs = (float*)smg;    // 128 x 132
#pragma unroll
    for (int i = 0; i < 2; i++)
#pragma unroll
        for (int j = 0; j < 8; j++)
#pragma unroll
            for (int r = 0; r < 4; r++) {
                int row = wm + i * 16 + (lane >> 2) + ((r >> 1) << 3);
                int col = wn + j * 8 + (lane & 3) * 2 + (r & 1);
                Cs[row * 132 + col] = acc[i][j][r];
            }
    __syncthreads();

    const int tx = tid & 15, ty = tid >> 4;
    float c[8][8];
#pragma unroll
    for (int i = 0; i < 8; i++)
#pragma unroll
        for (int j = 0; j < 8; j++)
            c[i][j] = Cs[(ty*8 + i) * 132 + tx*8 + j] + bias[n0 + tx*8 + j];

    const int b = m0 >> 11;
    const int srow = (m0 & (SS-1)) + ty * 8;
    if (which < 2) {
        float* dst = which ? g_Kt : g_Qt;
#pragma unroll
        for (int j = 0; j < 8; j++) {
            int n = n0 + tx*8 + j;
            int h = n >> 6, d = n & 63;
            float* p = dst + ((size_t)(b*NH + h)*DHD + d)*SS + srow;
            *(float4*)(p)     = make_float4(c[0][j], c[1][j], c[2][j], c[3][j]);
            *(float4*)(p + 4) = make_float4(c[4][j], c[5][j], c[6][j], c[7][j]);
        }
    } else if (which == 2) {
#pragma unroll
        for (int i = 0; i < 8; i++) {
            int n = n0 + tx*8;
            int h = n >> 6, d = n & 63;
            float* p = g_V + ((size_t)(b*NH + h)*SS + srow + i)*DHD + d;
            *(float4*)(p)     = make_float4(c[i][0], c[i][1], c[i][2], c[i][3]);
            *(float4*)(p + 4) = make_float4(c[i][4], c[i][5], c[i][6], c[i][7]);
        }
    } else {
#pragma unroll
        for (int i = 0; i < 8; i++) {
            float* p = outp + (size_t)(m0 + ty*8 + i) * EMBD + n0 + tx*8;
            *(float4*)(p)     = make_float4(c[i][0], c[i][1], c[i][2], c[i][3]);
            *(float4*)(p + 4) = make_float4(c[i][4], c[i][5], c[i][6], c[i][7]);
        }
    }
}

// ================= f32x2 helpers (attention) =================
__device__ __forceinline__ unsigned long long pk2(float a, float b) {
    unsigned long long r;
    asm("mov.b64 %0, {%1, %2};" : "=l"(r)
        : "r"(__float_as_uint(a)), "r"(__float_as_uint(b)));
    return r;
}
__device__ __forceinline__ void ffma2(unsigned long long& d,
                                      unsigned long long a, unsigned long long b) {
    asm("fma.rn.f32x2 %0, %1, %2, %0;" : "+l"(d) : "l"(a), "l"(b));
}
__device__ __forceinline__ unsigned long long mul2(unsigned long long a,
                                                   unsigned long long b) {
    unsigned long long r;
    asm("mul.rn.f32x2 %0, %1, %2;" : "=l"(r) : "l"(a), "l"(b));
    return r;
}
__device__ __forceinline__ void add2(unsigned long long& d, unsigned long long a) {
    asm("add.rn.f32x2 %0, %0, %1;" : "+l"(d) : "l"(a));
}
__device__ __forceinline__ float2 up2(unsigned long long v) {
    unsigned int lo, hi;
    asm("mov.b64 {%0, %1}, %2;" : "=r"(lo), "=r"(hi) : "l"(v));
    float2 r; r.x = __uint_as_float(lo); r.y = __uint_as_float(hi);
    return r;
}
__device__ __forceinline__ float ex2f(float x) {
    float r; asm("ex2.approx.f32 %0, %1;" : "=f"(r) : "f"(x)); return r;
}

// ================= flash attention (R6, unchanged) =================
#define QTS 128
#define VSS 68
#define PS  132
#define SMEM_FLOATS (64*QTS + 64*QTS + 128*VSS + 128*PS)

__global__ __launch_bounds__(256, 1)
void attn128()
{
    extern __shared__ float sm[];
    float* Qt = sm;
    float* Kt = Qt + 64*QTS;
    float* Vs = Kt + 64*QTS;
    float* P  = Vs + 128*VSS;

    const int tid  = threadIdx.x;
    const int tx   = tid & 15;
    const int ty   = tid >> 4;
    const int txLo = tx & 7;
    const int txHi = tx >> 3;
    const int q0   = blockIdx.x * 128;
    const int h    = blockIdx.y;
    const int b    = blockIdx.z;

    const float qscale = 0.125f * 1.44269504088896340736f;
    const size_t hb_t = (size_t)(b*NH + h) * DHD * SS;
    const size_t hb_v = (size_t)(b*NH + h) * SS * DHD;

    {
        const float* Qg = g_Qt + hb_t + q0;
#pragma unroll
        for (int i = 0; i < 8; i++) {
            int idx = tid + 256*i;
            int d = idx >> 5;
            int c4 = (idx & 31) << 2;
            float4 v = *(const float4*)(Qg + (size_t)d*SS + c4);
            v.x *= qscale; v.y *= qscale; v.z *= qscale; v.w *= qscale;
            *(float4*)(Qt + d*QTS + c4) = v;
        }
    }

    unsigned long long oacc[8][4];
    float mrow[8], lrow[8];
#pragma unroll
    for (int i = 0; i < 8; i++) {
        oacc[i][0] = oacc[i][1] = oacc[i][2] = oacc[i][3] = 0ull;
        mrow[i] = -3.0e38f; lrow[i] = 0.0f;
    }

    for (int kt = 0; kt < SS/128; kt++) {
        __syncthreads();
        {
            const float* Kg = g_Kt + hb_t + kt*128;
#pragma unroll
            for (int i = 0; i < 8; i++) {
                int idx = tid + 256*i;
                int d = idx >> 5;
                int c4 = (idx & 31) << 2;
                *(float4*)(Kt + d*QTS + c4) = *(const float4*)(Kg + (size_t)d*SS + c4);
            }
            const float* Vg = g_V + hb_v + (size_t)(kt*128)*DHD;
#pragma unroll
            for (int i = 0; i < 8; i++) {
                int idx = tid + 256*i;
                int r = idx >> 4;
                int d4 = (idx & 15) << 2;
                *(float4*)(Vs + r*VSS + d4) = *(const float4*)(Vg + r*DHD + d4);
            }
        }
        __syncthreads();

        unsigned long long sacc[8][4];
#pragma unroll
        for (int i = 0; i < 8; i++)
            sacc[i][0] = sacc[i][1] = sacc[i][2] = sacc[i][3] = 0ull;
#pragma unroll 8
        for (int d = 0; d < 64; d++) {
            float4 a0 = *(const float4*)(Qt + d*QTS + ty*8);
            float4 a1 = *(const float4*)(Qt + d*QTS + ty*8 + 4);
            ulonglong2 b0 = *(const ulonglong2*)(Kt + d*QTS + tx*8);
            ulonglong2 b1 = *(const ulonglong2*)(Kt + d*QTS + tx*8 + 4);
            float aq[8] = {a0.x, a0.y, a0.z, a0.w, a1.x, a1.y, a1.z, a1.w};
#pragma unroll
            for (int i = 0; i < 8; i++) {
                unsigned long long aa = pk2(aq[i], aq[i]);
                ffma2(sacc[i][0], aa, b0.x);
                ffma2(sacc[i][1], aa, b0.y);
                ffma2(sacc[i][2], aa, b1.x);
                ffma2(sacc[i][3], aa, b1.y);
            }
        }

#pragma unroll
        for (int i = 0; i < 8; i++) {
            float2 s01 = up2(sacc[i][0]), s23 = up2(sacc[i][1]);
            float2 s45 = up2(sacc[i][2]), s67 = up2(sacc[i][3]);
            float s[8] = {s01.x, s01.y, s23.x, s23.y, s45.x, s45.y, s67.x, s67.y};
            float rm = s[0];
#pragma unroll
            for (int j = 1; j < 8; j++) rm = fmaxf(rm, s[j]);
#pragma unroll
            for (int off = 1; off < 16; off <<= 1)
                rm = fmaxf(rm, __shfl_xor_sync(0xffffffffu, rm, off));
            float mn = fmaxf(mrow[i], rm);
            float corr = ex2f(mrow[i] - mn);
            mrow[i] = mn;
            float p[8], rs = 0.0f;
#pragma unroll
            for (int j = 0; j < 8; j++) { p[j] = ex2f(s[j] - mn); rs += p[j]; }
#pragma unroll
            for (int off = 1; off < 16; off <<= 1)
                rs += __shfl_xor_sync(0xffffffffu, rs, off);
            lrow[i] = lrow[i] * corr + rs;
            unsigned long long cc = pk2(corr, corr);
            oacc[i][0] = mul2(oacc[i][0], cc);
            oacc[i][1] = mul2(oacc[i][1], cc);
            oacc[i][2] = mul2(oacc[i][2], cc);
            oacc[i][3] = mul2(oacc[i][3], cc);
            *(float4*)(P + (ty*8 + i)*PS + tx*8)     = make_float4(p[0], p[1], p[2], p[3]);
            *(float4*)(P + (ty*8 + i)*PS + tx*8 + 4) = make_float4(p[4], p[5], p[6], p[7]);
        }
        __syncthreads();

#pragma unroll 2
        for (int kb = 0; kb < 16; kb++) {
            const int kbase = txHi*64 + kb*4;
            float4 pr[8];
#pragma unroll
            for (int i = 0; i < 8; i++)
                pr[i] = *(const float4*)(P + (ty*8 + i)*PS + kbase);
#pragma unroll
            for (int kk = 0; kk < 4; kk++) {
                const float* vrow = Vs + (kbase + kk)*VSS + txLo*8;
                ulonglong2 v0 = *(const ulonglong2*)(vrow);
                ulonglong2 v1 = *(const ulonglong2*)(vrow + 4);
#pragma unroll
                for (int i = 0; i < 8; i++) {
                    float pv = (kk == 0) ? pr[i].x : (kk == 1) ? pr[i].y
                             : (kk == 2) ? pr[i].z : pr[i].w;
                    unsigned long long aa = pk2(pv, pv);
                    ffma2(oacc[i][0], aa, v0.x);
                    ffma2(oacc[i][1], aa, v0.y);
                    ffma2(oacc[i][2], aa, v1.x);
                    ffma2(oacc[i][3], aa, v1.y);
                }
            }
        }
    }

#pragma unroll
    for (int i = 0; i < 8; i++)
#pragma unroll
        for (int c = 0; c < 4; c++) {
            unsigned long long other = __shfl_xor_sync(0xffffffffu, oacc[i][c], 8);
            add2(oacc[i][c], other);
        }

    if (txHi == 0) {
#pragma unroll
        for (int i = 0; i < 8; i++) {
            float rl = 1.0f / lrow[i];
            float2 p0 = up2(oacc[i][0]), p1 = up2(oacc[i][1]);
            float2 p2 = up2(oacc[i][2]), p3 = up2(oacc[i][3]);
            float* dst = g_C + ((size_t)b*SS + q0 + ty*8 + i)*EMBD + h*DHD + txLo*8;
            *(float4*)(dst)     = make_float4(p0.x*rl, p0.y*rl, p1.x*rl, p1.y*rl);
            *(float4*)(dst + 4) = make_float4(p2.x*rl, p2.y*rl, p3.x*rl, p3.y*rl);
        }
    }
}

// ---------------- launch ----------------
extern "C" void kernel_launch(void* const* d_in, const int* in_sizes, int n_in,
                              void* d_out, int out_size)
{
    (void)in_sizes; (void)n_in; (void)out_size;
    const float* x  = (const float*)d_in[0];
    const float* Wq = (const float*)d_in[1];
    const float* bq = (const float*)d_in[2];
    const float* Wk = (const float*)d_in[3];
    const float* bk = (const float*)d_in[4];
    const float* Wv = (const float*)d_in[5];
    const float* bv = (const float*)d_in[6];
    const float* Wo = (const float*)d_in[7];
    const float* bo = (const float*)d_in[8];
    float* out = (float*)d_out;

    static int attr_set = 0;
    if (!attr_set) {
        cudaFuncSetAttribute(attn128, cudaFuncAttributeMaxDynamicSharedMemorySize,
                             SMEM_FLOATS * (int)sizeof(float));
        cudaFuncSetAttribute(gemm_mma, cudaFuncAttributeMaxDynamicSharedMemorySize,
                             GEMM_SMEM);
        attr_set = 1;
    }

    conv_split<<<4096, 256>>>(x, 0);
    conv_wT<<<dim3(32, 32), dim3(32, 8)>>>(Wq, 0);
    conv_wT<<<dim3(32, 32), dim3(32, 8)>>>(Wk, 1);
    conv_wT<<<dim3(32, 32), dim3(32, 8)>>>(Wv, 2);
    conv_wT<<<dim3(32, 32), dim3(32, 8)>>>(Wo, 3);
    gemm_mma<<<dim3(8, 64, 3), 256, GEMM_SMEM>>>(0, bq, bk, bv, bo, out);
    attn128<<<dim3(SS/128, NH, BB), 256, SMEM_FLOATS * sizeof(float)>>>();
    conv_split<<<4096, 256>>>(nullptr, 1);
    gemm_mma<<<dim3(8, 64, 1), 256, GEMM_SMEM>>>(3, bq, bk, bv, bo, out);
}

// round 9
// speedup vs baseline: 5.0791x; 1.8619x over previous
#include <cuda_runtime.h>
#include <cstdint>

#define BB   4
#define SS   2048
#define EMBD 1024
#define NH   16
#define DHD  64
#define MTOT (BB*SS)   // 8192

// ---------------- scratch (device globals; allocation-free) ----------------
// split-bf16 operands (hi = trunc16(a), lo = rn(a - hi))
__device__ unsigned short g_xhi[(size_t)MTOT*EMBD], g_xlo[(size_t)MTOT*EMBD];
__device__ unsigned short g_whi[(size_t)4*EMBD*EMBD], g_wlo[(size_t)4*EMBD*EMBD]; // [which][n][k] (W^T)
__device__ unsigned short g_chi[(size_t)MTOT*EMBD], g_clo[(size_t)MTOT*EMBD];     // attention ctx
__device__ unsigned short g_qhi[(size_t)MTOT*EMBD], g_qlo[(size_t)MTOT*EMBD];     // [b,h,s,d], pre-scaled
__device__ unsigned short g_khi[(size_t)MTOT*EMBD], g_klo[(size_t)MTOT*EMBD];     // [b,h,s,d]
__device__ unsigned short g_vthi[(size_t)MTOT*EMBD], g_vtlo[(size_t)MTOT*EMBD];   // [b,h,d,s]

// ================= small PTX helpers =================
__device__ __forceinline__ uint32_t smem_u32(const void* p) {
    uint32_t a;
    asm("{ .reg .u64 t; cvta.to.shared.u64 t, %1; cvt.u32.u64 %0, t; }" : "=r"(a) : "l"(p));
    return a;
}
__device__ __forceinline__ void ldmx4(uint32_t* r, uint32_t addr) {
    asm volatile("ldmatrix.sync.aligned.m8n8.x4.shared.b16 {%0,%1,%2,%3}, [%4];"
        : "=r"(r[0]), "=r"(r[1]), "=r"(r[2]), "=r"(r[3]) : "r"(addr));
}
__device__ __forceinline__ void mma16816(float* d, const uint32_t* a, const uint32_t* b) {
    asm volatile("mma.sync.aligned.m16n8k16.row.col.f32.bf16.bf16.f32 "
        "{%0,%1,%2,%3}, {%4,%5,%6,%7}, {%8,%9}, {%0,%1,%2,%3};"
        : "+f"(d[0]), "+f"(d[1]), "+f"(d[2]), "+f"(d[3])
        : "r"(a[0]), "r"(a[1]), "r"(a[2]), "r"(a[3]), "r"(b[0]), "r"(b[1]));
}
#define CPA(dst, src) asm volatile("cp.async.cg.shared.global [%0], [%1], 16;" \
                                   :: "r"(dst), "l"(src) : "memory")
#define CPC()  asm volatile("cp.async.commit_group;" ::: "memory")
#define CPW1() asm volatile("cp.async.wait_group 1;" ::: "memory")
#define CPW0() asm volatile("cp.async.wait_group 0;" ::: "memory")

__device__ __forceinline__ float ex2f(float x) {
    float r; asm("ex2.approx.f32 %0, %1;" : "=f"(r) : "f"(x)); return r;
}
// pack two fp32 -> bf16x2: hi = bit-truncation, lo = rn(v - hi). lower short = first arg.
__device__ __forceinline__ unsigned int packhi(float a, float b) {
    return __byte_perm(__float_as_uint(a), __float_as_uint(b), 0x7632);
}
__device__ __forceinline__ unsigned int packlo(float a, float b) {
    float ha = __uint_as_float(__float_as_uint(a) & 0xFFFF0000u);
    float hb = __uint_as_float(__float_as_uint(b) & 0xFFFF0000u);
    unsigned int r;
    asm("cvt.rn.bf16x2.f32 %0, %1, %2;" : "=r"(r) : "f"(b - hb), "f"(a - ha));
    return r;
}

// ================= conversion kernels =================
__global__ void conv_split(const float* __restrict__ src)
{
    unsigned int* hi = (unsigned int*)g_xhi;
    unsigned int* lo = (unsigned int*)g_xlo;
    const size_t nP = (size_t)MTOT * EMBD / 2;
    for (size_t p = (size_t)blockIdx.x * blockDim.x + threadIdx.x; p < nP;
         p += (size_t)gridDim.x * blockDim.x) {
        float2 v = ((const float2*)src)[p];
        hi[p] = packhi(v.x, v.y);
        lo[p] = packlo(v.x, v.y);
    }
}

// W [K,N] fp32 -> transposed split-bf16 [which][n][k]
__global__ void conv_wT(const float* __restrict__ W, int which)
{
    __shared__ float sm[32][33];
    const int tx = threadIdx.x, ty = threadIdx.y;       // 32 x 8
    const int n0 = blockIdx.x * 32, k0 = blockIdx.y * 32;
#pragma unroll
    for (int i = 0; i < 4; i++)
        sm[ty + 8*i][tx] = W[(size_t)(k0 + ty + 8*i) * EMBD + n0 + tx];
    __syncthreads();
    unsigned short* ho = g_whi + (size_t)which * EMBD * EMBD;
    unsigned short* lo = g_wlo + (size_t)which * EMBD * EMBD;
#pragma unroll
    for (int i = 0; i < 4; i++) {
        int n = n0 + ty + 8*i, k = k0 + tx;
        float v = sm[tx][ty + 8*i];
        unsigned int u = __float_as_uint(v);
        float hf = __uint_as_float(u & 0xFFFF0000u);
        float lv = v - hf;
        unsigned short ls;
        asm("cvt.rn.bf16.f32 %0, %1;" : "=h"(ls) : "f"(lv));
        ho[(size_t)n * EMBD + k] = (unsigned short)(u >> 16);
        lo[(size_t)n * EMBD + k] = ls;
    }
}

// ================= mma.sync split-bf16 GEMM =================
#define KCH     32
#define NCH     (EMBD / KCH)     // 32
#define TROWB   80
#define TILEB   (128 * TROWB)    // 10240
#define STGB    (4 * TILEB)      // 40960
#define GEMM_SMEM (2 * STGB)     // 81920

__device__ __forceinline__ void issue_stage(uint32_t sb, int s,
    const unsigned short* __restrict__ Ahi, const unsigned short* __restrict__ Alo,
    const unsigned short* __restrict__ Bhi, const unsigned short* __restrict__ Blo,
    int m0, int n0, int kc, int tid)
{
    const uint32_t base = sb + s * STGB;
    const int koff = kc * KCH;
#pragma unroll
    for (int i = 0; i < 2; i++) {
        int lin = tid + 256 * i;
        int r = lin >> 2, u = lin & 3;
        uint32_t doff = (uint32_t)(r * TROWB + u * 16);
        size_t gA = (size_t)(m0 + r) * EMBD + koff + u * 8;
        size_t gB = (size_t)(n0 + r) * EMBD + koff + u * 8;
        CPA(base + doff,             Ahi + gA);
        CPA(base + TILEB + doff,     Alo + gA);
        CPA(base + 2*TILEB + doff,   Bhi + gB);
        CPA(base + 3*TILEB + doff,   Blo + gB);
    }
    CPC();
}

__global__ void gemm_mma(int whichBase,
             const float* __restrict__ bq, const float* __restrict__ bk,
             const float* __restrict__ bv, const float* __restrict__ bo,
             float* __restrict__ outp)
{
    extern __shared__ char smg[];
    const int tid  = threadIdx.x;
    const int lane = tid & 31, wid = tid >> 5;
    const int wm = (wid & 3) * 32;
    const int wn = (wid >> 2) * 64;
    const int which = whichBase + blockIdx.z;
    const int n0 = blockIdx.x * 128, m0 = blockIdx.y * 128;
    const uint32_t sb = smem_u32(smg);

    const unsigned short* Ahi = (which == 3) ? g_chi : g_xhi;
    const unsigned short* Alo = (which == 3) ? g_clo : g_xlo;
    const unsigned short* Bhi = g_whi + (size_t)which * EMBD * EMBD;
    const unsigned short* Blo = g_wlo + (size_t)which * EMBD * EMBD;
    const float* bias = (which == 0) ? bq : (which == 1) ? bk : (which == 2) ? bv : bo;

    float acc[2][8][4];
#pragma unroll
    for (int i = 0; i < 2; i++)
#pragma unroll
        for (int j = 0; j < 8; j++)
#pragma unroll
            for (int r = 0; r < 4; r++) acc[i][j][r] = 0.0f;

    const uint32_t aOff = (uint32_t)((lane & 15) * TROWB + ((lane >> 4) << 4));
    const uint32_t bOff = (uint32_t)(((lane & 7) + ((lane >> 4) << 3)) * TROWB
                                     + (((lane >> 3) & 1) << 4));

    issue_stage(sb, 0, Ahi, Alo, Bhi, Blo, m0, n0, 0, tid);

    for (int kc = 0; kc < NCH; kc++) {
        const int s = kc & 1;
        if (kc + 1 < NCH) {
            issue_stage(sb, s ^ 1, Ahi, Alo, Bhi, Blo, m0, n0, kc + 1, tid);
            CPW1();
        } else {
            CPW0();
        }
        __syncthreads();

        const uint32_t stg = sb + s * STGB;
#pragma unroll
        for (int k16 = 0; k16 < 2; k16++) {
            const uint32_t kb = k16 * 32;
            uint32_t ah[2][4], al[2][4], bh[4][4], bl[4][4];
#pragma unroll
            for (int i = 0; i < 2; i++) {
                uint32_t ra = stg + (uint32_t)((wm + i * 16) * TROWB) + kb + aOff;
                ldmx4(ah[i], ra);
                ldmx4(al[i], ra + TILEB);
            }
#pragma unroll
            for (int jj = 0; jj < 4; jj++) {
                uint32_t rb = stg + 2*TILEB + (uint32_t)((wn + jj * 16) * TROWB) + kb + bOff;
                ldmx4(bh[jj], rb);
                ldmx4(bl[jj], rb + TILEB);
            }
#pragma unroll
            for (int i = 0; i < 2; i++)
#pragma unroll
                for (int jj = 0; jj < 4; jj++) {
                    mma16816(acc[i][2*jj],   ah[i], &bh[jj][0]);
                    mma16816(acc[i][2*jj+1], ah[i], &bh[jj][2]);
                    mma16816(acc[i][2*jj],   ah[i], &bl[jj][0]);
                    mma16816(acc[i][2*jj+1], ah[i], &bl[jj][2]);
                    mma16816(acc[i][2*jj],   al[i], &bh[jj][0]);
                    mma16816(acc[i][2*jj+1], al[i], &bh[jj][2]);
                }
        }
        __syncthreads();
    }

    // stage fp32 tile through smem
    float* Cs = (float*)smg;    // 128 x 132
#pragma unroll
    for (int i = 0; i < 2; i++)
#pragma unroll
        for (int j = 0; j < 8; j++)
#pragma unroll
            for (int r = 0; r < 4; r++) {
                int row = wm + i * 16 + (lane >> 2) + ((r >> 1) << 3);
                int col = wn + j * 8 + (lane & 3) * 2 + (r & 1);
                Cs[row * 132 + col] = acc[i][j][r];
            }
    __syncthreads();

    const int tx = tid & 15, ty = tid >> 4;
    float c[8][8];
#pragma unroll
    for (int i = 0; i < 8; i++)
#pragma unroll
        for (int j = 0; j < 8; j++)
            c[i][j] = Cs[(ty*8 + i) * 132 + tx*8 + j] + bias[n0 + tx*8 + j];

    const int b = m0 >> 11;
    const int srow = (m0 & (SS-1)) + ty * 8;
    if (which < 2) {
        // Q (scaled) / K -> split bf16 [b,h,s,d]
        const float qs = (which == 0) ? 0.125f * 1.44269504088896340736f : 1.0f;
        unsigned short* dh = which ? g_khi : g_qhi;
        unsigned short* dl = which ? g_klo : g_qlo;
        const int hh = (n0 + tx*8) >> 6, d0 = (n0 + tx*8) & 63;
#pragma unroll
        for (int i = 0; i < 8; i++) {
            size_t base = ((size_t)(b*NH + hh)*SS + srow + i)*DHD + d0;
            unsigned int h4[4], l4[4];
#pragma unroll
            for (int jp = 0; jp < 4; jp++) {
                float v0 = c[i][2*jp] * qs, v1 = c[i][2*jp+1] * qs;
                h4[jp] = packhi(v0, v1);
                l4[jp] = packlo(v0, v1);
            }
            *(uint4*)(dh + base) = make_uint4(h4[0], h4[1], h4[2], h4[3]);
            *(uint4*)(dl + base) = make_uint4(l4[0], l4[1], l4[2], l4[3]);
        }
    } else if (which == 2) {
        // V -> transposed split bf16 [b,h,d,s]
#pragma unroll
        for (int j = 0; j < 8; j++) {
            int n = n0 + tx*8 + j, hh = n >> 6, d = n & 63;
            size_t base = ((size_t)(b*NH + hh)*DHD + d)*SS + srow;
            unsigned int h4[4], l4[4];
#pragma unroll
            for (int ip = 0; ip < 4; ip++) {
                h4[ip] = packhi(c[2*ip][j], c[2*ip+1][j]);
                l4[ip] = packlo(c[2*ip][j], c[2*ip+1][j]);
            }
            *(uint4*)(g_vthi + base) = make_uint4(h4[0], h4[1], h4[2], h4[3]);
            *(uint4*)(g_vtlo + base) = make_uint4(l4[0], l4[1], l4[2], l4[3]);
        }
    } else {
#pragma unroll
        for (int i = 0; i < 8; i++) {
            float* p = outp + (size_t)(m0 + ty*8 + i) * EMBD + n0 + tx*8;
            *(float4*)(p)     = make_float4(c[i][0], c[i][1], c[i][2], c[i][3]);
            *(float4*)(p + 4) = make_float4(c[i][4], c[i][5], c[i][6], c[i][7]);
        }
    }
}

// ================= tensor-core flash attention =================
// 128 q-rows/CTA, 8 warps x 16 rows, kv chunks of 64, double-buffered cp.async.
// smem tile: 64 rows x 144B (72 shorts). Stage = Khi|Klo|Vthi|Vtlo = 4 x 9216.
#define AROW  144
#define ATILE (64 * AROW)        // 9216
#define ASTG  (4 * ATILE)        // 36864
#define ATTN_SMEM (2 * ASTG)     // 73728

__global__ __launch_bounds__(256, 1) void attn_mma()
{
    extern __shared__ char sma[];
    const uint32_t sb = smem_u32(sma);
    const int tid = threadIdx.x, lane = tid & 31, wid = tid >> 5;
    const int wm = wid * 16;
    const int q0 = blockIdx.x * 128, h = blockIdx.y, b = blockIdx.z;
    const size_t hb = (size_t)(b*NH + h) * SS * DHD;   // head base (both layouts)

    // ---- stage Q tile (hi at 0, lo at +18432) and pull into register frags ----
#pragma unroll
    for (int i = 0; i < 4; i++) {
        int lin = tid + 256 * i;
        int r = lin >> 3, u = lin & 7;
        uint32_t d = sb + (uint32_t)(r * AROW + u * 16);
        size_t g = hb + (size_t)(q0 + r) * DHD + u * 8;
        CPA(d,         g_qhi + g);
        CPA(d + 18432, g_qlo + g);
    }
    CPC(); CPW0(); __syncthreads();

    uint32_t qh[4][4], ql[4][4];
    const uint32_t aoff = (uint32_t)((lane & 15) * AROW + ((lane >> 4) << 4));
#pragma unroll
    for (int t = 0; t < 4; t++) {
        uint32_t ra = sb + (uint32_t)(wm * AROW) + aoff + t * 32;
        ldmx4(qh[t], ra);
        ldmx4(ql[t], ra + 18432);
    }
    __syncthreads();   // Q staging consumed; smem belongs to the pipeline now

    float oacc[8][4];
#pragma unroll
    for (int j = 0; j < 8; j++)
#pragma unroll
        for (int r = 0; r < 4; r++) oacc[j][r] = 0.0f;
    float mrw[2] = {-3.0e38f, -3.0e38f}, lrw[2] = {0.0f, 0.0f};

    const uint32_t boff = (uint32_t)(((lane & 7) + ((lane >> 4) << 3)) * AROW
                                     + (((lane >> 3) & 1) << 4));

    // prologue: chunk 0 -> stage 0
    {
        uint32_t base = sb;
#pragma unroll
        for (int i = 0; i < 2; i++) {
            int lin = tid + 256 * i;
            int r = lin >> 3, u = lin & 7;
            uint32_t doff = (uint32_t)(r * AROW + u * 16);
            size_t gk = hb + (size_t)r * DHD + u * 8;
            size_t gv = hb + (size_t)r * SS + u * 8;
            CPA(base + doff,             g_khi  + gk);
            CPA(base + ATILE + doff,     g_klo  + gk);
            CPA(base + 2*ATILE + doff,   g_vthi + gv);
            CPA(base + 3*ATILE + doff,   g_vtlo + gv);
        }
        CPC();
    }

    for (int kt = 0; kt < SS/64; kt++) {
        const int s = kt & 1;
        if (kt + 1 < SS/64) {
            uint32_t base = sb + (s ^ 1) * ASTG;
#pragma unroll
            for (int i = 0; i < 2; i++) {
                int lin = tid + 256 * i;
                int r = lin >> 3, u = lin & 7;
                uint32_t doff = (uint32_t)(r * AROW + u * 16);
                size_t gk = hb + (size_t)((kt+1)*64 + r) * DHD + u * 8;
                size_t gv = hb + (size_t)r * SS + (kt+1)*64 + u * 8;
                CPA(base + doff,             g_khi  + gk);
                CPA(base + ATILE + doff,     g_klo  + gk);
                CPA(base + 2*ATILE + doff,   g_vthi + gv);
                CPA(base + 3*ATILE + doff,   g_vtlo + gv);
            }
            CPC(); CPW1();
        } else {
            CPW0();
        }
        __syncthreads();

        const uint32_t stg = sb + s * ASTG;

        // ---- S = Q@K^T (3-term split), warp computes 16 x 64 ----
        float sacc[8][4];
#pragma unroll
        for (int j = 0; j < 8; j++)
#pragma unroll
            for (int r = 0; r < 4; r++) sacc[j][r] = 0.0f;
#pragma unroll
        for (int t = 0; t < 4; t++)
#pragma unroll
            for (int jj = 0; jj < 4; jj++) {
                uint32_t rb = stg + (uint32_t)(jj * 16 * AROW) + boff + t * 32;
                uint32_t kh[4], kl[4];
                ldmx4(kh, rb);
                ldmx4(kl, rb + ATILE);
                mma16816(sacc[2*jj],   qh[t], &kh[0]);
                mma16816(sacc[2*jj+1], qh[t], &kh[2]);
                mma16816(sacc[2*jj],   qh[t], &kl[0]);
                mma16816(sacc[2*jj+1], qh[t], &kl[2]);
                mma16816(sacc[2*jj],   ql[t], &kh[0]);
                mma16816(sacc[2*jj+1], ql[t], &kh[2]);
            }

        // ---- online softmax (base-2; scale folded into Q) ----
#pragma unroll
        for (int rh = 0; rh < 2; rh++) {
            float rm = sacc[0][2*rh];
#pragma unroll
            for (int j = 0; j < 8; j++)
                rm = fmaxf(rm, fmaxf(sacc[j][2*rh], sacc[j][2*rh+1]));
            rm = fmaxf(rm, __shfl_xor_sync(0xffffffffu, rm, 1));
            rm = fmaxf(rm, __shfl_xor_sync(0xffffffffu, rm, 2));
            float mn = fmaxf(mrw[rh], rm);
            float corr = ex2f(mrw[rh] - mn);
            mrw[rh] = mn;
            float rs = 0.0f;
#pragma unroll
            for (int j = 0; j < 8; j++) {
                float p0 = ex2f(sacc[j][2*rh]   - mn);
                float p1 = ex2f(sacc[j][2*rh+1] - mn);
                sacc[j][2*rh] = p0; sacc[j][2*rh+1] = p1;
                rs += p0 + p1;
            }
            rs += __shfl_xor_sync(0xffffffffu, rs, 1);
            rs += __shfl_xor_sync(0xffffffffu, rs, 2);
            lrw[rh] = lrw[rh] * corr + rs;
#pragma unroll
            for (int j = 0; j < 8; j++) {
                oacc[j][2*rh]   *= corr;
                oacc[j][2*rh+1] *= corr;
            }
        }

        // ---- PV (3-term split): A-frags built from p registers ----
#pragma unroll
        for (int t = 0; t < 4; t++) {
            uint32_t ah[4], al[4];
            ah[0] = packhi(sacc[2*t][0],   sacc[2*t][1]);
            al[0] = packlo(sacc[2*t][0],   sacc[2*t][1]);
            ah[1] = packhi(sacc[2*t][2],   sacc[2*t][3]);
            al[1] = packlo(sacc[2*t][2],   sacc[2*t][3]);
            ah[2] = packhi(sacc[2*t+1][0], sacc[2*t+1][1]);
            al[2] = packlo(sacc[2*t+1][0], sacc[2*t+1][1]);
            ah[3] = packhi(sacc[2*t+1][2], sacc[2*t+1][3]);
            al[3] = packlo(sacc[2*t+1][2], sacc[2*t+1][3]);
#pragma unroll
            for (int jj = 0; jj < 4; jj++) {
                uint32_t rb = stg + 2*ATILE + (uint32_t)(jj * 16 * AROW) + boff + t * 32;
                uint32_t vh[4], vl[4];
                ldmx4(vh, rb);
                ldmx4(vl, rb + ATILE);
                mma16816(oacc[2*jj],   ah, &vh[0]);
                mma16816(oacc[2*jj+1], ah, &vh[2]);
                mma16816(oacc[2*jj],   ah, &vl[0]);
                mma16816(oacc[2*jj+1], ah, &vl[2]);
                mma16816(oacc[2*jj],   al, &vh[0]);
                mma16816(oacc[2*jj+1], al, &vh[2]);
            }
        }
        __syncthreads();
    }

    // ---- epilogue: normalize, split to bf16 hi/lo, write ctx [row][e] ----
    const float rl0 = 1.0f / lrw[0], rl1 = 1.0f / lrw[1];
    const size_t row0 = (size_t)b*SS + q0 + wm + (lane >> 2);
    const size_t row1 = row0 + 8;
    const int col = h * DHD + (lane & 3) * 2;
#pragma unroll
    for (int jj = 0; jj < 8; jj++) {
        float o0 = oacc[jj][0] * rl0, o1 = oacc[jj][1] * rl0;
        float o2 = oacc[jj][2] * rl1, o3 = oacc[jj][3] * rl1;
        size_t c0 = row0 * EMBD + col + jj * 8;
        size_t c1 = row1 * EMBD + col + jj * 8;
        *(unsigned int*)(g_chi + c0) = packhi(o0, o1);
        *(unsigned int*)(g_clo + c0) = packlo(o0, o1);
        *(unsigned int*)(g_chi + c1) = packhi(o2, o3);
        *(unsigned int*)(g_clo + c1) = packlo(o2, o3);
    }
}

// ---------------- launch ----------------
extern "C" void kernel_launch(void* const* d_in, const int* in_sizes, int n_in,
                              void* d_out, int out_size)
{
    (void)in_sizes; (void)n_in; (void)out_size;
    const float* x  = (const float*)d_in[0];
    const float* Wq = (const float*)d_in[1];
    const float* bq = (const float*)d_in[2];
    const float* Wk = (const float*)d_in[3];
    const float* bk = (const float*)d_in[4];
    const float* Wv = (const float*)d_in[5];
    const float* bv = (const float*)d_in[6];
    const float* Wo = (const float*)d_in[7];
    const float* bo = (const float*)d_in[8];
    float* out = (float*)d_out;

    static int attr_set = 0;
    if (!attr_set) {
        cudaFuncSetAttribute(gemm_mma, cudaFuncAttributeMaxDynamicSharedMemorySize,
                             GEMM_SMEM);
        cudaFuncSetAttribute(attn_mma, cudaFuncAttributeMaxDynamicSharedMemorySize,
                             ATTN_SMEM);
        attr_set = 1;
    }

    conv_split<<<4096, 256>>>(x);
    conv_wT<<<dim3(32, 32), dim3(32, 8)>>>(Wq, 0);
    conv_wT<<<dim3(32, 32), dim3(32, 8)>>>(Wk, 1);
    conv_wT<<<dim3(32, 32), dim3(32, 8)>>>(Wv, 2);
    conv_wT<<<dim3(32, 32), dim3(32, 8)>>>(Wo, 3);
    gemm_mma<<<dim3(8, 64, 3), 256, GEMM_SMEM>>>(0, bq, bk, bv, bo, out);
    attn_mma<<<dim3(SS/128, NH, BB), 256, ATTN_SMEM>>>();
    gemm_mma<<<dim3(8, 64, 1), 256, GEMM_SMEM>>>(3, bq, bk, bv, bo, out);
}

// round 10
// speedup vs baseline: 5.1155x; 1.0072x over previous
#include <cuda_runtime.h>
#include <cstdint>

#define BB   4
#define SS   2048
#define EMBD 1024
#define NH   16
#define DHD  64
#define MTOT (BB*SS)   // 8192

// ---------------- scratch (device globals; allocation-free) ----------------
__device__ unsigned short g_xhi[(size_t)MTOT*EMBD], g_xlo[(size_t)MTOT*EMBD];
__device__ unsigned short g_whi[(size_t)4*EMBD*EMBD], g_wlo[(size_t)4*EMBD*EMBD]; // [which][n][k] (W^T)
__device__ unsigned short g_chi[(size_t)MTOT*EMBD], g_clo[(size_t)MTOT*EMBD];     // attention ctx
__device__ unsigned short g_qhi[(size_t)MTOT*EMBD], g_qlo[(size_t)MTOT*EMBD];     // [b,h,s,d], pre-scaled
__device__ unsigned short g_khi[(size_t)MTOT*EMBD], g_klo[(size_t)MTOT*EMBD];     // [b,h,s,d]
__device__ unsigned short g_vthi[(size_t)MTOT*EMBD], g_vtlo[(size_t)MTOT*EMBD];   // [b,h,d,s]

// ================= small PTX helpers =================
__device__ __forceinline__ uint32_t smem_u32(const void* p) {
    uint32_t a;
    asm("{ .reg .u64 t; cvta.to.shared.u64 t, %1; cvt.u32.u64 %0, t; }" : "=r"(a) : "l"(p));
    return a;
}
__device__ __forceinline__ void ldmx4(uint32_t* r, uint32_t addr) {
    asm volatile("ldmatrix.sync.aligned.m8n8.x4.shared.b16 {%0,%1,%2,%3}, [%4];"
        : "=r"(r[0]), "=r"(r[1]), "=r"(r[2]), "=r"(r[3]) : "r"(addr));
}
__device__ __forceinline__ void mma16816(float* d, const uint32_t* a, const uint32_t* b) {
    asm volatile("mma.sync.aligned.m16n8k16.row.col.f32.bf16.bf16.f32 "
        "{%0,%1,%2,%3}, {%4,%5,%6,%7}, {%8,%9}, {%0,%1,%2,%3};"
        : "+f"(d[0]), "+f"(d[1]), "+f"(d[2]), "+f"(d[3])
        : "r"(a[0]), "r"(a[1]), "r"(a[2]), "r"(a[3]), "r"(b[0]), "r"(b[1]));
}
#define CPA(dst, src) asm volatile("cp.async.cg.shared.global [%0], [%1], 16;" \
                                   :: "r"(dst), "l"(src) : "memory")
#define CPC()  asm volatile("cp.async.commit_group;" ::: "memory")
#define CPW1() asm volatile("cp.async.wait_group 1;" ::: "memory")
#define CPW0() asm volatile("cp.async.wait_group 0;" ::: "memory")

__device__ __forceinline__ float ex2f(float x) {
    float r; asm("ex2.approx.f32 %0, %1;" : "=f"(r) : "f"(x)); return r;
}
__device__ __forceinline__ unsigned int packhi(float a, float b) {
    return __byte_perm(__float_as_uint(a), __float_as_uint(b), 0x7632);
}
__device__ __forceinline__ unsigned int packlo(float a, float b) {
    float ha = __uint_as_float(__float_as_uint(a) & 0xFFFF0000u);
    float hb = __uint_as_float(__float_as_uint(b) & 0xFFFF0000u);
    unsigned int r;
    asm("cvt.rn.bf16x2.f32 %0, %1, %2;" : "=r"(r) : "f"(b - hb), "f"(a - ha));
    return r;
}

// ================= conversion kernels =================
__global__ void conv_split(const float* __restrict__ src)
{
    unsigned int* hi = (unsigned int*)g_xhi;
    unsigned int* lo = (unsigned int*)g_xlo;
    const size_t nP = (size_t)MTOT * EMBD / 2;
    for (size_t p = (size_t)blockIdx.x * blockDim.x + threadIdx.x; p < nP;
         p += (size_t)gridDim.x * blockDim.x) {
        float2 v = ((const float2*)src)[p];
        hi[p] = packhi(v.x, v.y);
        lo[p] = packlo(v.x, v.y);
    }
}

// all four W [K,N] fp32 -> transposed split-bf16 [z][n][k]
__global__ void conv_wT(const float* __restrict__ Wq, const float* __restrict__ Wk,
                        const float* __restrict__ Wv, const float* __restrict__ Wo)
{
    __shared__ float sm[32][33];
    const int z = blockIdx.z;
    const float* W = (z == 0) ? Wq : (z == 1) ? Wk : (z == 2) ? Wv : Wo;
    const int tx = threadIdx.x, ty = threadIdx.y;       // 32 x 8
    const int n0 = blockIdx.x * 32, k0 = blockIdx.y * 32;
#pragma unroll
    for (int i = 0; i < 4; i++)
        sm[ty + 8*i][tx] = W[(size_t)(k0 + ty + 8*i) * EMBD + n0 + tx];
    __syncthreads();
    unsigned short* ho = g_whi + (size_t)z * EMBD * EMBD;
    unsigned short* lo = g_wlo + (size_t)z * EMBD * EMBD;
#pragma unroll
    for (int i = 0; i < 4; i++) {
        int n = n0 + ty + 8*i, k = k0 + tx;
        float v = sm[tx][ty + 8*i];
        unsigned int u = __float_as_uint(v);
        float hf = __uint_as_float(u & 0xFFFF0000u);
        float lv = v - hf;
        unsigned short ls;
        asm("cvt.rn.bf16.f32 %0, %1;" : "=h"(ls) : "f"(lv));
        ho[(size_t)n * EMBD + k] = (unsigned short)(u >> 16);
        lo[(size_t)n * EMBD + k] = ls;
    }
}

// ================= mma.sync split-bf16 GEMM (K-chunk 64) =================
#define KCH     64
#define NCH     (EMBD / KCH)     // 16
#define TROWB   144
#define TILEB   (128 * TROWB)    // 18432
#define STGB    (4 * TILEB)      // 73728
#define GEMM_SMEM (2 * STGB)     // 147456

__device__ __forceinline__ void issue_stage(uint32_t sb, int s,
    const unsigned short* __restrict__ Ahi, const unsigned short* __restrict__ Alo,
    const unsigned short* __restrict__ Bhi, const unsigned short* __restrict__ Blo,
    int m0, int n0, int kc, int tid)
{
    const uint32_t base = sb + s * STGB;
    const int koff = kc * KCH;
#pragma unroll
    for (int i = 0; i < 4; i++) {
        int lin = tid + 256 * i;
        int r = lin >> 3, u = lin & 7;
        uint32_t doff = (uint32_t)(r * TROWB + u * 16);
        size_t gA = (size_t)(m0 + r) * EMBD + koff + u * 8;
        size_t gB = (size_t)(n0 + r) * EMBD + koff + u * 8;
        CPA(base + doff,             Ahi + gA);
        CPA(base + TILEB + doff,     Alo + gA);
        CPA(base + 2*TILEB + doff,   Bhi + gB);
        CPA(base + 3*TILEB + doff,   Blo + gB);
    }
    CPC();
}

__global__ void gemm_mma(int whichBase,
             const float* __restrict__ bq, const float* __restrict__ bk,
             const float* __restrict__ bv, const float* __restrict__ bo,
             float* __restrict__ outp)
{
    extern __shared__ char smg[];
    const int tid  = threadIdx.x;
    const int lane = tid & 31, wid = tid >> 5;
    const int wm = (wid & 3) * 32;
    const int wn = (wid >> 2) * 64;
    const int which = whichBase + blockIdx.z;
    const int n0 = blockIdx.x * 128, m0 = blockIdx.y * 128;
    const uint32_t sb = smem_u32(smg);

    const unsigned short* Ahi = (which == 3) ? g_chi : g_xhi;
    const unsigned short* Alo = (which == 3) ? g_clo : g_xlo;
    const unsigned short* Bhi = g_whi + (size_t)which * EMBD * EMBD;
    const unsigned short* Blo = g_wlo + (size_t)which * EMBD * EMBD;
    const float* bias = (which == 0) ? bq : (which == 1) ? bk : (which == 2) ? bv : bo;

    float acc[2][8][4];
#pragma unroll
    for (int i = 0; i < 2; i++)
#pragma unroll
        for (int j = 0; j < 8; j++)
#pragma unroll
            for (int r = 0; r < 4; r++) acc[i][j][r] = 0.0f;

    const uint32_t aOff = (uint32_t)((lane & 15) * TROWB + ((lane >> 4) << 4));
    const uint32_t bOff = (uint32_t)(((lane & 7) + ((lane >> 4) << 3)) * TROWB
                                     + (((lane >> 3) & 1) << 4));

    issue_stage(sb, 0, Ahi, Alo, Bhi, Blo, m0, n0, 0, tid);

    for (int kc = 0; kc < NCH; kc++) {
        const int s = kc & 1;
        if (kc + 1 < NCH) {
            issue_stage(sb, s ^ 1, Ahi, Alo, Bhi, Blo, m0, n0, kc + 1, tid);
            CPW1();
        } else {
            CPW0();
        }
        __syncthreads();

        const uint32_t stg = sb + s * STGB;
#pragma unroll
        for (int k16 = 0; k16 < 4; k16++) {
            const uint32_t kb = k16 * 32;
            uint32_t ah[2][4], al[2][4], bh[4][4], bl[4][4];
#pragma unroll
            for (int i = 0; i < 2; i++) {
                uint32_t ra = stg + (uint32_t)((wm + i * 16) * TROWB) + kb + aOff;
                ldmx4(ah[i], ra);
                ldmx4(al[i], ra + TILEB);
            }
#pragma unroll
            for (int jj = 0; jj < 4; jj++) {
                uint32_t rb = stg + 2*TILEB + (uint32_t)((wn + jj * 16) * TROWB) + kb + bOff;
                ldmx4(bh[jj], rb);
                ldmx4(bl[jj], rb + TILEB);
            }
#pragma unroll
            for (int i = 0; i < 2; i++)
#pragma unroll
                for (int jj = 0; jj < 4; jj++) {
                    mma16816(acc[i][2*jj],   ah[i], &bh[jj][0]);
                    mma16816(acc[i][2*jj+1], ah[i], &bh[jj][2]);
                    mma16816(acc[i][2*jj],   ah[i], &bl[jj][0]);
                    mma16816(acc[i][2*jj+1], ah[i], &bl[jj][2]);
                    mma16816(acc[i][2*jj],   al[i], &bh[jj][0]);
                    mma16816(acc[i][2*jj+1], al[i], &bh[jj][2]);
                }
        }
        __syncthreads();
    }

    // stage fp32 tile through smem
    float* Cs = (float*)smg;    // 128 x 132
#pragma unroll
    for (int i = 0; i < 2; i++)
#pragma unroll
        for (int j = 0; j < 8; j++)
#pragma unroll
            for (int r = 0; r < 4; r++) {
                int row = wm + i * 16 + (lane >> 2) + ((r >> 1) << 3);
                int col = wn + j * 8 + (lane & 3) * 2 + (r & 1);
                Cs[row * 132 + col] = acc[i][j][r];
            }
    __syncthreads();

    const int tx = tid & 15, ty = tid >> 4;
    float c[8][8];
#pragma unroll
    for (int i = 0; i < 8; i++)
#pragma unroll
        for (int j = 0; j < 8; j++)
            c[i][j] = Cs[(ty*8 + i) * 132 + tx*8 + j] + bias[n0 + tx*8 + j];

    const int b = m0 >> 11;
    const int srow = (m0 & (SS-1)) + ty * 8;
    if (which < 2) {
        const float qs = (which == 0) ? 0.125f * 1.44269504088896340736f : 1.0f;
        unsigned short* dh = which ? g_khi : g_qhi;
        unsigned short* dl = which ? g_klo : g_qlo;
        const int hh = (n0 + tx*8) >> 6, d0 = (n0 + tx*8) & 63;
#pragma unroll
        for (int i = 0; i < 8; i++) {
            size_t base = ((size_t)(b*NH + hh)*SS + srow + i)*DHD + d0;
            unsigned int h4[4], l4[4];
#pragma unroll
            for (int jp = 0; jp < 4; jp++) {
                float v0 = c[i][2*jp] * qs, v1 = c[i][2*jp+1] * qs;
                h4[jp] = packhi(v0, v1);
                l4[jp] = packlo(v0, v1);
            }
            *(uint4*)(dh + base) = make_uint4(h4[0], h4[1], h4[2], h4[3]);
            *(uint4*)(dl + base) = make_uint4(l4[0], l4[1], l4[2], l4[3]);
        }
    } else if (which == 2) {
#pragma unroll
        for (int j = 0; j < 8; j++) {
            int n = n0 + tx*8 + j, hh = n >> 6, d = n & 63;
            size_t base = ((size_t)(b*NH + hh)*DHD + d)*SS + srow;
            unsigned int h4[4], l4[4];
#pragma unroll
            for (int ip = 0; ip < 4; ip++) {
                h4[ip] = packhi(c[2*ip][j], c[2*ip+1][j]);
                l4[ip] = packlo(c[2*ip][j], c[2*ip+1][j]);
            }
            *(uint4*)(g_vthi + base) = make_uint4(h4[0], h4[1], h4[2], h4[3]);
            *(uint4*)(g_vtlo + base) = make_uint4(l4[0], l4[1], l4[2], l4[3]);
        }
    } else {
#pragma unroll
        for (int i = 0; i < 8; i++) {
            float* p = outp + (size_t)(m0 + ty*8 + i) * EMBD + n0 + tx*8;
            *(float4*)(p)     = make_float4(c[i][0], c[i][1], c[i][2], c[i][3]);
            *(float4*)(p + 4) = make_float4(c[i][4], c[i][5], c[i][6], c[i][7]);
        }
    }
}

// ================= tensor-core flash attention (kv-chunk 128) =================
// 128 q-rows/CTA, 8 warps x 16 rows. Stage: Khi|Klo (128 rows x 144B each) +
// Vthi|Vtlo (64 d-rows x 272B each).
#define KROW  144
#define KTILE (128 * KROW)       // 18432
#define VROW  272
#define VTILE (64 * VROW)        // 17408
#define ASTG  (2*KTILE + 2*VTILE)  // 71680
#define ATTN_SMEM (2 * ASTG)       // 143360

__global__ __launch_bounds__(256, 1) void attn_mma()
{
    extern __shared__ char sma[];
    const uint32_t sb = smem_u32(sma);
    const int tid = threadIdx.x, lane = tid & 31, wid = tid >> 5;
    const int wm = wid * 16;
    const int q0 = blockIdx.x * 128, h = blockIdx.y, b = blockIdx.z;
    const size_t hb = (size_t)(b*NH + h) * SS * DHD;

    // ---- stage Q tile (hi @0, lo @KTILE) and pull into register frags ----
#pragma unroll
    for (int i = 0; i < 4; i++) {
        int lin = tid + 256 * i;
        int r = lin >> 3, u = lin & 7;
        uint32_t d = sb + (uint32_t)(r * KROW + u * 16);
        size_t g = hb + (size_t)(q0 + r) * DHD + u * 8;
        CPA(d,         g_qhi + g);
        CPA(d + KTILE, g_qlo + g);
    }
    CPC(); CPW0(); __syncthreads();

    uint32_t qh[4][4], ql[4][4];
    const uint32_t aoff = (uint32_t)((lane & 15) * KROW + ((lane >> 4) << 4));
#pragma unroll
    for (int t = 0; t < 4; t++) {
        uint32_t ra = sb + (uint32_t)(wm * KROW) + aoff + t * 32;
        ldmx4(qh[t], ra);
        ldmx4(ql[t], ra + KTILE);
    }
    __syncthreads();

    float oacc[8][4];
#pragma unroll
    for (int j = 0; j < 8; j++)
#pragma unroll
        for (int r = 0; r < 4; r++) oacc[j][r] = 0.0f;
    float mrw[2] = {-3.0e38f, -3.0e38f}, lrw[2] = {0.0f, 0.0f};

    const uint32_t bK = (uint32_t)(((lane & 7) + ((lane >> 4) << 3)) * KROW
                                   + (((lane >> 3) & 1) << 4));
    const uint32_t bV = (uint32_t)(((lane & 7) + ((lane >> 4) << 3)) * VROW
                                   + (((lane >> 3) & 1) << 4));

    // prologue: chunk 0 -> stage 0
    {
        uint32_t base = sb;
#pragma unroll
        for (int i = 0; i < 4; i++) {       // K rows (128 x 8 segs)
            int lin = tid + 256 * i;
            int r = lin >> 3, u = lin & 7;
            uint32_t doff = (uint32_t)(r * KROW + u * 16);
            size_t gk = hb + (size_t)r * DHD + u * 8;
            CPA(base + doff,         g_khi + gk);
            CPA(base + KTILE + doff, g_klo + gk);
        }
#pragma unroll
        for (int i = 0; i < 4; i++) {       // V rows (64 x 16 segs)
            int lin = tid + 256 * i;
            int r = lin >> 4, u = lin & 15;
            uint32_t doff = (uint32_t)(r * VROW + u * 16);
            size_t gv = hb + (size_t)r * SS + u * 8;
            CPA(base + 2*KTILE + doff,         g_vthi + gv);
            CPA(base + 2*KTILE + VTILE + doff, g_vtlo + gv);
        }
        CPC();
    }

    for (int kt = 0; kt < SS/128; kt++) {
        const int s = kt & 1;
        if (kt + 1 < SS/128) {
            uint32_t base = sb + (s ^ 1) * ASTG;
#pragma unroll
            for (int i = 0; i < 4; i++) {
                int lin = tid + 256 * i;
                int r = lin >> 3, u = lin & 7;
                uint32_t doff = (uint32_t)(r * KROW + u * 16);
                size_t gk = hb + (size_t)((kt+1)*128 + r) * DHD + u * 8;
                CPA(base + doff,         g_khi + gk);
                CPA(base + KTILE + doff, g_klo + gk);
            }
#pragma unroll
            for (int i = 0; i < 4; i++) {
                int lin = tid + 256 * i;
                int r = lin >> 4, u = lin & 15;
                uint32_t doff = (uint32_t)(r * VROW + u * 16);
                size_t gv = hb + (size_t)r * SS + (kt+1)*128 + u * 8;
                CPA(base + 2*KTILE + doff,         g_vthi + gv);
                CPA(base + 2*KTILE + VTILE + doff, g_vtlo + gv);
            }
            CPC(); CPW1();
        } else {
            CPW0();
        }
        __syncthreads();

        const uint32_t stg = sb + s * ASTG;

        // ---- S = Q@K^T (3-term split), warp computes 16 x 128 ----
        float sacc[16][4];
#pragma unroll
        for (int j = 0; j < 16; j++)
#pragma unroll
            for (int r = 0; r < 4; r++) sacc[j][r] = 0.0f;
#pragma unroll
        for (int t = 0; t < 4; t++)
#pragma unroll
            for (int jj = 0; jj < 8; jj++) {
                uint32_t rb = stg + (uint32_t)(jj * 16 * KROW) + bK + t * 32;
                uint32_t kh[4], kl[4];
                ldmx4(kh, rb);
                ldmx4(kl, rb + KTILE);
                mma16816(sacc[2*jj],   qh[t], &kh[0]);
                mma16816(sacc[2*jj+1], qh[t], &kh[2]);
                mma16816(sacc[2*jj],   qh[t], &kl[0]);
                mma16816(sacc[2*jj+1], qh[t], &kl[2]);
                mma16816(sacc[2*jj],   ql[t], &kh[0]);
                mma16816(sacc[2*jj+1], ql[t], &kh[2]);
            }

        // ---- online softmax (base-2; scale folded into Q) ----
#pragma unroll
        for (int rh = 0; rh < 2; rh++) {
            float rm = sacc[0][2*rh];
#pragma unroll
            for (int j = 0; j < 16; j++)
                rm = fmaxf(rm, fmaxf(sacc[j][2*rh], sacc[j][2*rh+1]));
            rm = fmaxf(rm, __shfl_xor_sync(0xffffffffu, rm, 1));
            rm = fmaxf(rm, __shfl_xor_sync(0xffffffffu, rm, 2));
            float mn = fmaxf(mrw[rh], rm);
            float corr = ex2f(mrw[rh] - mn);
            mrw[rh] = mn;
            float rs = 0.0f;
#pragma unroll
            for (int j = 0; j < 16; j++) {
                float p0 = ex2f(sacc[j][2*rh]   - mn);
                float p1 = ex2f(sacc[j][2*rh+1] - mn);
                sacc[j][2*rh] = p0; sacc[j][2*rh+1] = p1;
                rs += p0 + p1;
            }
            rs += __shfl_xor_sync(0xffffffffu, rs, 1);
            rs += __shfl_xor_sync(0xffffffffu, rs, 2);
            lrw[rh] = lrw[rh] * corr + rs;
#pragma unroll
            for (int j = 0; j < 8; j++) {
                oacc[j][2*rh]   *= corr;
                oacc[j][2*rh+1] *= corr;
            }
        }

        // ---- PV (3-term split): A-frags repacked from p registers ----
#pragma unroll
        for (int t = 0; t < 8; t++) {
            uint32_t ah[4], al[4];
            ah[0] = packhi(sacc[2*t][0],   sacc[2*t][1]);
            al[0] = packlo(sacc[2*t][0],   sacc[2*t][1]);
            ah[1] = packhi(sacc[2*t][2],   sacc[2*t][3]);
            al[1] = packlo(sacc[2*t][2],   sacc[2*t][3]);
            ah[2] = packhi(sacc[2*t+1][0], sacc[2*t+1][1]);
            al[2] = packlo(sacc[2*t+1][0], sacc[2*t+1][1]);
            ah[3] = packhi(sacc[2*t+1][2], sacc[2*t+1][3]);
            al[3] = packlo(sacc[2*t+1][2], sacc[2*t+1][3]);
#pragma unroll
            for (int jj = 0; jj < 4; jj++) {
                uint32_t rb = stg + 2*KTILE + (uint32_t)(jj * 16 * VROW) + bV + t * 32;
                uint32_t vh[4], vl[4];
                ldmx4(vh, rb);
                ldmx4(vl, rb + VTILE);
                mma16816(oacc[2*jj],   ah, &vh[0]);
                mma16816(oacc[2*jj+1], ah, &vh[2]);
                mma16816(oacc[2*jj],   ah, &vl[0]);
                mma16816(oacc[2*jj+1], ah, &vl[2]);
                mma16816(oacc[2*jj],   al, &vh[0]);
                mma16816(oacc[2*jj+1], al, &vh[2]);
            }
        }
        __syncthreads();
    }

    // ---- epilogue: normalize, split to bf16 hi/lo, write ctx [row][e] ----
    const float rl0 = 1.0f / lrw[0], rl1 = 1.0f / lrw[1];
    const size_t row0 = (size_t)b*SS + q0 + wm + (lane >> 2);
    const size_t row1 = row0 + 8;
    const int col = h * DHD + (lane & 3) * 2;
#pragma unroll
    for (int jj = 0; jj < 8; jj++) {
        float o0 = oacc[jj][0] * rl0, o1 = oacc[jj][1] * rl0;
        float o2 = oacc[jj][2] * rl1, o3 = oacc[jj][3] * rl1;
        size_t c0 = row0 * EMBD + col + jj * 8;
        size_t c1 = row1 * EMBD + col + jj * 8;
        *(unsigned int*)(g_chi + c0) = packhi(o0, o1);
        *(unsigned int*)(g_clo + c0) = packlo(o0, o1);
        *(unsigned int*)(g_chi + c1) = packhi(o2, o3);
        *(unsigned int*)(g_clo + c1) = packlo(o2, o3);
    }
}

// ---------------- launch ----------------
extern "C" void kernel_launch(void* const* d_in, const int* in_sizes, int n_in,
                              void* d_out, int out_size)
{
    (void)in_sizes; (void)n_in; (void)out_size;
    const float* x  = (const float*)d_in[0];
    const float* Wq = (const float*)d_in[1];
    const float* bq = (const float*)d_in[2];
    const float* Wk = (const float*)d_in[3];
    const float* bk = (const float*)d_in[4];
    const float* Wv = (const float*)d_in[5];
    const float* bv = (const float*)d_in[6];
    const float* Wo = (const float*)d_in[7];
    const float* bo = (const float*)d_in[8];
    float* out = (float*)d_out;

    static int attr_set = 0;
    if (!attr_set) {
        cudaFuncSetAttribute(gemm_mma, cudaFuncAttributeMaxDynamicSharedMemorySize,
                             GEMM_SMEM);
        cudaFuncSetAttribute(attn_mma, cudaFuncAttributeMaxDynamicSharedMemorySize,
                             ATTN_SMEM);
        attr_set = 1;
    }

    conv_split<<<4096, 256>>>(x);
    conv_wT<<<dim3(32, 32, 4), dim3(32, 8)>>>(Wq, Wk, Wv, Wo);
    gemm_mma<<<dim3(8, 64, 3), 256, GEMM_SMEM>>>(0, bq, bk, bv, bo, out);
    attn_mma<<<dim3(SS/128, NH, BB), 256, ATTN_SMEM>>>();
    gemm_mma<<<dim3(8, 64, 1), 256, GEMM_SMEM>>>(3, bq, bk, bv, bo, out);
}

// round 15
// speedup vs baseline: 5.2813x; 1.0324x over previous
#include <cuda_runtime.h>
#include <cstdint>

#define BB   4
#define SS   2048
#define EMBD 1024
#define NH   16
#define DHD  64
#define MTOT (BB*SS)   // 8192

// ---------------- scratch (device globals; allocation-free) ----------------
__device__ unsigned short g_xhi[(size_t)MTOT*EMBD], g_xlo[(size_t)MTOT*EMBD];
__device__ unsigned short g_whi[(size_t)4*EMBD*EMBD], g_wlo[(size_t)4*EMBD*EMBD]; // [which][n][k] (W^T)
__device__ unsigned short g_chi[(size_t)MTOT*EMBD], g_clo[(size_t)MTOT*EMBD];     // attention ctx
__device__ unsigned short g_qhi[(size_t)MTOT*EMBD], g_qlo[(size_t)MTOT*EMBD];     // [b,h,s,d], pre-scaled
__device__ unsigned short g_khi[(size_t)MTOT*EMBD], g_klo[(size_t)MTOT*EMBD];     // [b,h,s,d]
__device__ unsigned short g_vthi[(size_t)MTOT*EMBD], g_vtlo[(size_t)MTOT*EMBD];   // [b,h,d,s]

// ================= small PTX helpers =================
__device__ __forceinline__ uint32_t smem_u32(const void* p) {
    uint32_t a;
    asm("{ .reg .u64 t; cvta.to.shared.u64 t, %1; cvt.u32.u64 %0, t; }" : "=r"(a) : "l"(p));
    return a;
}
__device__ __forceinline__ void ldmx4(uint32_t* r, uint32_t addr) {
    asm volatile("ldmatrix.sync.aligned.m8n8.x4.shared.b16 {%0,%1,%2,%3}, [%4];"
        : "=r"(r[0]), "=r"(r[1]), "=r"(r[2]), "=r"(r[3]) : "r"(addr));
}
__device__ __forceinline__ void mma16816(float* d, const uint32_t* a, const uint32_t* b) {
    asm volatile("mma.sync.aligned.m16n8k16.row.col.f32.bf16.bf16.f32 "
        "{%0,%1,%2,%3}, {%4,%5,%6,%7}, {%8,%9}, {%0,%1,%2,%3};"
        : "+f"(d[0]), "+f"(d[1]), "+f"(d[2]), "+f"(d[3])
        : "r"(a[0]), "r"(a[1]), "r"(a[2]), "r"(a[3]), "r"(b[0]), "r"(b[1]));
}
#define CPA(dst, src) asm volatile("cp.async.cg.shared.global [%0], [%1], 16;" \
                                   :: "r"(dst), "l"(src) : "memory")
#define CPC()  asm volatile("cp.async.commit_group;" ::: "memory")
#define CPW1() asm volatile("cp.async.wait_group 1;" ::: "memory")
#define CPW0() asm volatile("cp.async.wait_group 0;" ::: "memory")

__device__ __forceinline__ float ex2f(float x) {
    float r; asm("ex2.approx.f32 %0, %1;" : "=f"(r) : "f"(x)); return r;
}
__device__ __forceinline__ unsigned int packhi(float a, float b) {
    return __byte_perm(__float_as_uint(a), __float_as_uint(b), 0x7632);
}
__device__ __forceinline__ unsigned int packlo(float a, float b) {
    float ha = __uint_as_float(__float_as_uint(a) & 0xFFFF0000u);
    float hb = __uint_as_float(__float_as_uint(b) & 0xFFFF0000u);
    unsigned int r;
    asm("cvt.rn.bf16x2.f32 %0, %1, %2;" : "=r"(r) : "f"(b - hb), "f"(a - ha));
    return r;
}

// ================= conversion kernels =================
__global__ void conv_split(const float* __restrict__ src)
{
    unsigned int* hi = (unsigned int*)g_xhi;
    unsigned int* lo = (unsigned int*)g_xlo;
    const size_t nP = (size_t)MTOT * EMBD / 2;
    for (size_t p = (size_t)blockIdx.x * blockDim.x + threadIdx.x; p < nP;
         p += (size_t)gridDim.x * blockDim.x) {
        float2 v = ((const float2*)src)[p];
        hi[p] = packhi(v.x, v.y);
        lo[p] = packlo(v.x, v.y);
    }
}

// all four W [K,N] fp32 -> transposed split-bf16 [z][n][k]
__global__ void conv_wT(const float* __restrict__ Wq, const float* __restrict__ Wk,
                        const float* __restrict__ Wv, const float* __restrict__ Wo)
{
    __shared__ float sm[32][33];
    const int z = blockIdx.z;
    const float* W = (z == 0) ? Wq : (z == 1) ? Wk : (z == 2) ? Wv : Wo;
    const int tx = threadIdx.x, ty = threadIdx.y;       // 32 x 8
    const int n0 = blockIdx.x * 32, k0 = blockIdx.y * 32;
#pragma unroll
    for (int i = 0; i < 4; i++)
        sm[ty + 8*i][tx] = W[(size_t)(k0 + ty + 8*i) * EMBD + n0 + tx];
    __syncthreads();
    unsigned short* ho = g_whi + (size_t)z * EMBD * EMBD;
    unsigned short* lo = g_wlo + (size_t)z * EMBD * EMBD;
#pragma unroll
    for (int i = 0; i < 4; i++) {
        int n = n0 + ty + 8*i, k = k0 + tx;
        float v = sm[tx][ty + 8*i];
        unsigned int u = __float_as_uint(v);
        float hf = __uint_as_float(u & 0xFFFF0000u);
        float lv = v - hf;
        unsigned short ls;
        asm("cvt.rn.bf16.f32 %0, %1;" : "=h"(ls) : "f"(lv));
        ho[(size_t)n * EMBD + k] = (unsigned short)(u >> 16);
        lo[(size_t)n * EMBD + k] = ls;
    }
}

// ================= mma.sync split-bf16 GEMM (K-chunk 32, 2 CTA/SM) =================
#define KCH     32
#define NCH     (EMBD / KCH)     // 32
#define TROWB   80
#define TILEB   (128 * TROWB)    // 10240
#define STGB    (4 * TILEB)      // 40960
#define GEMM_SMEM (2 * STGB)     // 81920 (2 CTAs = 163840 <= 227KB)

__device__ __forceinline__ void issue_stage(uint32_t sb, int s,
    const unsigned short* __restrict__ Ahi, const unsigned short* __restrict__ Alo,
    const unsigned short* __restrict__ Bhi, const unsigned short* __restrict__ Blo,
    int m0, int n0, int kc, int tid)
{
    const uint32_t base = sb + s * STGB;
    const int koff = kc * KCH;
#pragma unroll
    for (int i = 0; i < 2; i++) {
        int lin = tid + 256 * i;
        int r = lin >> 2, u = lin & 3;
        uint32_t doff = (uint32_t)(r * TROWB + u * 16);
        size_t gA = (size_t)(m0 + r) * EMBD + koff + u * 8;
        size_t gB = (size_t)(n0 + r) * EMBD + koff + u * 8;
        CPA(base + doff,             Ahi + gA);
        CPA(base + TILEB + doff,     Alo + gA);
        CPA(base + 2*TILEB + doff,   Bhi + gB);
        CPA(base + 3*TILEB + doff,   Blo + gB);
    }
    CPC();
}

__global__ __launch_bounds__(256, 2) void gemm_mma(int whichBase,
             const float* __restrict__ bq, const float* __restrict__ bk,
             const float* __restrict__ bv, const float* __restrict__ bo,
             float* __restrict__ outp)
{
    extern __shared__ char smg[];
    const int tid  = threadIdx.x;
    const int lane = tid & 31, wid = tid >> 5;
    const int wm = (wid & 3) * 32;
    const int wn = (wid >> 2) * 64;
    const int which = whichBase + blockIdx.z;
    const int n0 = blockIdx.x * 128, m0 = blockIdx.y * 128;
    const uint32_t sb = smem_u32(smg);

    const unsigned short* Ahi = (which == 3) ? g_chi : g_xhi;
    const unsigned short* Alo = (which == 3) ? g_clo : g_xlo;
    const unsigned short* Bhi = g_whi + (size_t)which * EMBD * EMBD;
    const unsigned short* Blo = g_wlo + (size_t)which * EMBD * EMBD;
    const float* bias = (which == 0) ? bq : (which == 1) ? bk : (which == 2) ? bv : bo;

    float acc[2][8][4];
#pragma unroll
    for (int i = 0; i < 2; i++)
#pragma unroll
        for (int j = 0; j < 8; j++)
#pragma unroll
            for (int r = 0; r < 4; r++) acc[i][j][r] = 0.0f;

    const uint32_t aOff = (uint32_t)((lane & 15) * TROWB + ((lane >> 4) << 4));
    const uint32_t bOff = (uint32_t)(((lane & 7) + ((lane >> 4) << 3)) * TROWB
                                     + (((lane >> 3) & 1) << 4));

    issue_stage(sb, 0, Ahi, Alo, Bhi, Blo, m0, n0, 0, tid);

    for (int kc = 0; kc < NCH; kc++) {
        const int s = kc & 1;
        if (kc + 1 < NCH) {
            issue_stage(sb, s ^ 1, Ahi, Alo, Bhi, Blo, m0, n0, kc + 1, tid);
            CPW1();
        } else {
            CPW0();
        }
        __syncthreads();

        const uint32_t stg = sb + s * STGB;
#pragma unroll
        for (int k16 = 0; k16 < 2; k16++) {
            const uint32_t kb = k16 * 32;
            uint32_t ah[2][4], al[2][4];
#pragma unroll
            for (int i = 0; i < 2; i++) {
                uint32_t ra = stg + (uint32_t)((wm + i * 16) * TROWB) + kb + aOff;
                ldmx4(ah[i], ra);
                ldmx4(al[i], ra + TILEB);
            }
#pragma unroll
            for (int jj = 0; jj < 4; jj++) {
                uint32_t bh[4], bl[4];
                uint32_t rb = stg + 2*TILEB + (uint32_t)((wn + jj * 16) * TROWB) + kb + bOff;
                ldmx4(bh, rb);
                ldmx4(bl, rb + TILEB);
#pragma unroll
                for (int i = 0; i < 2; i++) {
                    mma16816(acc[i][2*jj],   ah[i], &bh[0]);
                    mma16816(acc[i][2*jj+1], ah[i], &bh[2]);
                    mma16816(acc[i][2*jj],   ah[i], &bl[0]);
                    mma16816(acc[i][2*jj+1], ah[i], &bl[2]);
                    mma16816(acc[i][2*jj],   al[i], &bh[0]);
                    mma16816(acc[i][2*jj+1], al[i], &bh[2]);
                }
            }
        }
        __syncthreads();
    }

    // stage fp32 tile through smem (fits in the 80KB dynamic smem)
    float* Cs = (float*)smg;    // 128 x 132
#pragma unroll
    for (int i = 0; i < 2; i++)
#pragma unroll
        for (int j = 0; j < 8; j++)
#pragma unroll
            for (int r = 0; r < 4; r++) {
                int row = wm + i * 16 + (lane >> 2) + ((r >> 1) << 3);
                int col = wn + j * 8 + (lane & 3) * 2 + (r & 1);
                Cs[row * 132 + col] = acc[i][j][r];
            }
    __syncthreads();

    const int tx = tid & 15, ty = tid >> 4;
    float c[8][8];
#pragma unroll
    for (int i = 0; i < 8; i++)
#pragma unroll
        for (int j = 0; j < 8; j++)
            c[i][j] = Cs[(ty*8 + i) * 132 + tx*8 + j] + bias[n0 + tx*8 + j];

    const int b = m0 >> 11;
    const int srow = (m0 & (SS-1)) + ty * 8;
    if (which < 2) {
        const float qs = (which == 0) ? 0.125f * 1.44269504088896340736f : 1.0f;
        unsigned short* dh = which ? g_khi : g_qhi;
        unsigned short* dl = which ? g_klo : g_qlo;
        const int hh = (n0 + tx*8) >> 6, d0 = (n0 + tx*8) & 63;
#pragma unroll
        for (int i = 0; i < 8; i++) {
            size_t base = ((size_t)(b*NH + hh)*SS + srow + i)*DHD + d0;
            unsigned int h4[4], l4[4];
#pragma unroll
            for (int jp = 0; jp < 4; jp++) {
                float v0 = c[i][2*jp] * qs, v1 = c[i][2*jp+1] * qs;
                h4[jp] = packhi(v0, v1);
                l4[jp] = packlo(v0, v1);
            }
            *(uint4*)(dh + base) = make_uint4(h4[0], h4[1], h4[2], h4[3]);
            *(uint4*)(dl + base) = make_uint4(l4[0], l4[1], l4[2], l4[3]);
        }
    } else if (which == 2) {
#pragma unroll
        for (int j = 0; j < 8; j++) {
            int n = n0 + tx*8 + j, hh = n >> 6, d = n & 63;
            size_t base = ((size_t)(b*NH + hh)*DHD + d)*SS + srow;
            unsigned int h4[4], l4[4];
#pragma unroll
            for (int ip = 0; ip < 4; ip++) {
                h4[ip] = packhi(c[2*ip][j], c[2*ip+1][j]);
                l4[ip] = packlo(c[2*ip][j], c[2*ip+1][j]);
            }
            *(uint4*)(g_vthi + base) = make_uint4(h4[0], h4[1], h4[2], h4[3]);
            *(uint4*)(g_vtlo + base) = make_uint4(l4[0], l4[1], l4[2], l4[3]);
        }
    } else {
#pragma unroll
        for (int i = 0; i < 8; i++) {
            float* p = outp + (size_t)(m0 + ty*8 + i) * EMBD + n0 + tx*8;
            *(float4*)(p)     = make_float4(c[i][0], c[i][1], c[i][2], c[i][3]);
            *(float4*)(p + 4) = make_float4(c[i][4], c[i][5], c[i][6], c[i][7]);
        }
    }
}

// ================= tensor-core flash attention (kv-chunk 128, unchanged) =================
#define KROW  144
#define KTILE (128 * KROW)       // 18432
#define VROW  272
#define VTILE (64 * VROW)        // 17408
#define ASTG  (2*KTILE + 2*VTILE)  // 71680
#define ATTN_SMEM (2 * ASTG)       // 143360

__global__ __launch_bounds__(256, 1) void attn_mma()
{
    extern __shared__ char sma[];
    const uint32_t sb = smem_u32(sma);
    const int tid = threadIdx.x, lane = tid & 31, wid = tid >> 5;
    const int wm = wid * 16;
    const int q0 = blockIdx.x * 128, h = blockIdx.y, b = blockIdx.z;
    const size_t hb = (size_t)(b*NH + h) * SS * DHD;

#pragma unroll
    for (int i = 0; i < 4; i++) {
        int lin = tid + 256 * i;
        int r = lin >> 3, u = lin & 7;
        uint32_t d = sb + (uint32_t)(r * KROW + u * 16);
        size_t g = hb + (size_t)(q0 + r) * DHD + u * 8;
        CPA(d,         g_qhi + g);
        CPA(d + KTILE, g_qlo + g);
    }
    CPC(); CPW0(); __syncthreads();

    uint32_t qh[4][4], ql[4][4];
    const uint32_t aoff = (uint32_t)((lane & 15) * KROW + ((lane >> 4) << 4));
#pragma unroll
    for (int t = 0; t < 4; t++) {
        uint32_t ra = sb + (uint32_t)(wm * KROW) + aoff + t * 32;
        ldmx4(qh[t], ra);
        ldmx4(ql[t], ra + KTILE);
    }
    __syncthreads();

    float oacc[8][4];
#pragma unroll
    for (int j = 0; j < 8; j++)
#pragma unroll
        for (int r = 0; r < 4; r++) oacc[j][r] = 0.0f;
    float mrw[2] = {-3.0e38f, -3.0e38f}, lrw[2] = {0.0f, 0.0f};

    const uint32_t bK = (uint32_t)(((lane & 7) + ((lane >> 4) << 3)) * KROW
                                   + (((lane >> 3) & 1) << 4));
    const uint32_t bV = (uint32_t)(((lane & 7) + ((lane >> 4) << 3)) * VROW
                                   + (((lane >> 3) & 1) << 4));

    {
        uint32_t base = sb;
#pragma unroll
        for (int i = 0; i < 4; i++) {
            int lin = tid + 256 * i;
            int r = lin >> 3, u = lin & 7;
            uint32_t doff = (uint32_t)(r * KROW + u * 16);
            size_t gk = hb + (size_t)r * DHD + u * 8;
            CPA(base + doff,         g_khi + gk);
            CPA(base + KTILE + doff, g_klo + gk);
        }
#pragma unroll
        for (int i = 0; i < 4; i++) {
            int lin = tid + 256 * i;
            int r = lin >> 4, u = lin & 15;
            uint32_t doff = (uint32_t)(r * VROW + u * 16);
            size_t gv = hb + (size_t)r * SS + u * 8;
            CPA(base + 2*KTILE + doff,         g_vthi + gv);
            CPA(base + 2*KTILE + VTILE + doff, g_vtlo + gv);
        }
        CPC();
    }

    for (int kt = 0; kt < SS/128; kt++) {
        const int s = kt & 1;
        if (kt + 1 < SS/128) {
            uint32_t base = sb + (s ^ 1) * ASTG;
#pragma unroll
            for (int i = 0; i < 4; i++) {
                int lin = tid + 256 * i;
                int r = lin >> 3, u = lin & 7;
                uint32_t doff = (uint32_t)(r * KROW + u * 16);
                size_t gk = hb + (size_t)((kt+1)*128 + r) * DHD + u * 8;
                CPA(base + doff,         g_khi + gk);
                CPA(base + KTILE + doff, g_klo + gk);
            }
#pragma unroll
            for (int i = 0; i < 4; i++) {
                int lin = tid + 256 * i;
                int r = lin >> 4, u = lin & 15;
                uint32_t doff = (uint32_t)(r * VROW + u * 16);
                size_t gv = hb + (size_t)r * SS + (kt+1)*128 + u * 8;
                CPA(base + 2*KTILE + doff,         g_vthi + gv);
                CPA(base + 2*KTILE + VTILE + doff, g_vtlo + gv);
            }
            CPC(); CPW1();
        } else {
            CPW0();
        }
        __syncthreads();

        const uint32_t stg = sb + s * ASTG;

        float sacc[16][4];
#pragma unroll
        for (int j = 0; j < 16; j++)
#pragma unroll
            for (int r = 0; r < 4; r++) sacc[j][r] = 0.0f;
#pragma unroll
        for (int t = 0; t < 4; t++)
#pragma unroll
            for (int jj = 0; jj < 8; jj++) {
                uint32_t rb = stg + (uint32_t)(jj * 16 * KROW) + bK + t * 32;
                uint32_t kh[4], kl[4];
                ldmx4(kh, rb);
                ldmx4(kl, rb + KTILE);
                mma16816(sacc[2*jj],   qh[t], &kh[0]);
                mma16816(sacc[2*jj+1], qh[t], &kh[2]);
                mma16816(sacc[2*jj],   qh[t], &kl[0]);
                mma16816(sacc[2*jj+1], qh[t], &kl[2]);
                mma16816(sacc[2*jj],   ql[t], &kh[0]);
                mma16816(sacc[2*jj+1], ql[t], &kh[2]);
            }

#pragma unroll
        for (int rh = 0; rh < 2; rh++) {
            float rm = sacc[0][2*rh];
#pragma unroll
            for (int j = 0; j < 16; j++)
                rm = fmaxf(rm, fmaxf(sacc[j][2*rh], sacc[j][2*rh+1]));
            rm = fmaxf(rm, __shfl_xor_sync(0xffffffffu, rm, 1));
            rm = fmaxf(rm, __shfl_xor_sync(0xffffffffu, rm, 2));
            float mn = fmaxf(mrw[rh], rm);
            float corr = ex2f(mrw[rh] - mn);
            mrw[rh] = mn;
            float rs = 0.0f;
#pragma unroll
            for (int j = 0; j < 16; j++) {
                float p0 = ex2f(sacc[j][2*rh]   - mn);
                float p1 = ex2f(sacc[j][2*rh+1] - mn);
                sacc[j][2*rh] = p0; sacc[j][2*rh+1] = p1;
                rs += p0 + p1;
            }
            rs += __shfl_xor_sync(0xffffffffu, rs, 1);
            rs += __shfl_xor_sync(0xffffffffu, rs, 2);
            lrw[rh] = lrw[rh] * corr + rs;
#pragma unroll
            for (int j = 0; j < 8; j++) {
                oacc[j][2*rh]   *= corr;
                oacc[j][2*rh+1] *= corr;
            }
        }

#pragma unroll
        for (int t = 0; t < 8; t++) {
            uint32_t ah[4], al[4];
            ah[0] = packhi(sacc[2*t][0],   sacc[2*t][1]);
            al[0] = packlo(sacc[2*t][0],   sacc[2*t][1]);
            ah[1] = packhi(sacc[2*t][2],   sacc[2*t][3]);
            al[1] = packlo(sacc[2*t][2],   sacc[2*t][3]);
            ah[2] = packhi(sacc[2*t+1][0], sacc[2*t+1][1]);
            al[2] = packlo(sacc[2*t+1][0], sacc[2*t+1][1]);
            ah[3] = packhi(sacc[2*t+1][2], sacc[2*t+1][3]);
            al[3] = packlo(sacc[2*t+1][2], sacc[2*t+1][3]);
#pragma unroll
            for (int jj = 0; jj < 4; jj++) {
                uint32_t rb = stg + 2*KTILE + (uint32_t)(jj * 16 * VROW) + bV + t * 32;
                uint32_t vh[4], vl[4];
                ldmx4(vh, rb);
                ldmx4(vl, rb + VTILE);
                mma16816(oacc[2*jj],   ah, &vh[0]);
                mma16816(oacc[2*jj+1], ah, &vh[2]);
                mma16816(oacc[2*jj],   ah, &vl[0]);
                mma16816(oacc[2*jj+1], ah, &vl[2]);
                mma16816(oacc[2*jj],   al, &vh[0]);
                mma16816(oacc[2*jj+1], al, &vh[2]);
            }
        }
        __syncthreads();
    }

    const float rl0 = 1.0f / lrw[0], rl1 = 1.0f / lrw[1];
    const size_t row0 = (size_t)b*SS + q0 + wm + (lane >> 2);
    const size_t row1 = row0 + 8;
    const int col = h * DHD + (lane & 3) * 2;
#pragma unroll
    for (int jj = 0; jj < 8; jj++) {
        float o0 = oacc[jj][0] * rl0, o1 = oacc[jj][1] * rl0;
        float o2 = oacc[jj][2] * rl1, o3 = oacc[jj][3] * rl1;
        size_t c0 = row0 * EMBD + col + jj * 8;
        size_t c1 = row1 * EMBD + col + jj * 8;
        *(unsigned int*)(g_chi + c0) = packhi(o0, o1);
        *(unsigned int*)(g_clo + c0) = packlo(o0, o1);
        *(unsigned int*)(g_chi + c1) = packhi(o2, o3);
        *(unsigned int*)(g_clo + c1) = packlo(o2, o3);
    }
}

// ---------------- launch ----------------
extern "C" void kernel_launch(void* const* d_in, const int* in_sizes, int n_in,
                              void* d_out, int out_size)
{
    (void)in_sizes; (void)n_in; (void)out_size;
    const float* x  = (const float*)d_in[0];
    const float* Wq = (const float*)d_in[1];
    const float* bq = (const float*)d_in[2];
    const float* Wk = (const float*)d_in[3];
    const float* bk = (const float*)d_in[4];
    const float* Wv = (const float*)d_in[5];
    const float* bv = (const float*)d_in[6];
    const float* Wo = (const float*)d_in[7];
    const float* bo = (const float*)d_in[8];
    float* out = (float*)d_out;

    static int attr_set = 0;
    if (!attr_set) {
        cudaFuncSetAttribute(gemm_mma, cudaFuncAttributeMaxDynamicSharedMemorySize,
                             GEMM_SMEM);
        cudaFuncSetAttribute(attn_mma, cudaFuncAttributeMaxDynamicSharedMemorySize,
                             ATTN_SMEM);
        attr_set = 1;
    }

    conv_split<<<4096, 256>>>(x);
    conv_wT<<<dim3(32, 32, 4), dim3(32, 8)>>>(Wq, Wk, Wv, Wo);
    gemm_mma<<<dim3(8, 64, 3), 256, GEMM_SMEM>>>(0, bq, bk, bv, bo, out);
    attn_mma<<<dim3(SS/128, NH, BB), 256, ATTN_SMEM>>>();
    gemm_mma<<<dim3(8, 64, 1), 256, GEMM_SMEM>>>(3, bq, bk, bv, bo, out);
}